// round 3
// baseline (speedup 1.0000x reference)
#include <cuda_runtime.h>
#include <math.h>

// Problem constants
#define Ed 1024
#define Nd 16
#define Kd 4
#define Rd 64
#define Bd 2
#define Ld 2048
#define Pd 96          // R + 2N
#define CLs 64         // chunk length for scan
#define NCH 32         // L / CLs

// ---------------- scratch (static device memory; no allocation) ----------------
__device__ __align__(128) float g_z[(size_t)Bd * Ld * Ed];
__device__ __align__(128) float g_params[(size_t)Bd * Ld * Pd];
__device__ __align__(128) float g_dt[(size_t)Bd * Ld * Ed];
__device__ __align__(128) float g_u[(size_t)Bd * Ld * Ed];
__device__ __align__(128) float g_g[(size_t)Bd * Ld * Ed];
__device__ __align__(128) float g_hend[(size_t)Bd * NCH * Ed * Nd];
__device__ __align__(128) float g_P[(size_t)Bd * NCH * Ed * Nd];
__device__ __align__(128) float g_hcarry[(size_t)Bd * NCH * Ed * Nd];

__device__ __forceinline__ float softplus_f(float v) {
    return v > 20.f ? v : log1pf(expf(v));
}
__device__ __forceinline__ float silu_f(float v) {
    return v / (1.f + expf(-v));
}

// ---------------- fp32 SGEMM: Y[M,N] = X[M,K] @ W[N,K]^T (+epilogue) ----------------
// Block tile 128x128, BK=16, 256 threads, 8x8 per thread.
// EPI: 0 = none, 1 = softplus(acc + bias[col])
template <int EPI>
__global__ __launch_bounds__(256)
void sgemm_nt(const float* __restrict__ X, int ldx,
              const float* __restrict__ W,   // N x K row-major (ld = K)
              float* __restrict__ Y, int ldy,
              int M, int N, int K,
              const float* __restrict__ bias)
{
    __shared__ float Xs[16][128];
    __shared__ float Ws[16][128];
    const int tid = threadIdx.x;
    const int tx = tid & 15, ty = tid >> 4;
    const int bm = blockIdx.y * 128;
    const int bn = blockIdx.x * 128;
    const int lrow = tid >> 2;          // 0..63
    const int lcol = (tid & 3) << 2;    // 0,4,8,12

    float acc[8][8];
#pragma unroll
    for (int i = 0; i < 8; ++i)
#pragma unroll
        for (int j = 0; j < 8; ++j) acc[i][j] = 0.f;

    for (int k0 = 0; k0 < K; k0 += 16) {
#pragma unroll
        for (int p = 0; p < 2; ++p) {
            int m = lrow + p * 64;
            const float4 v = *reinterpret_cast<const float4*>(
                &X[(size_t)(bm + m) * ldx + k0 + lcol]);
            Xs[lcol + 0][m] = v.x; Xs[lcol + 1][m] = v.y;
            Xs[lcol + 2][m] = v.z; Xs[lcol + 3][m] = v.w;
        }
#pragma unroll
        for (int p = 0; p < 2; ++p) {
            int n = lrow + p * 64;
            float4 v = make_float4(0.f, 0.f, 0.f, 0.f);
            if (bn + n < N)
                v = *reinterpret_cast<const float4*>(
                    &W[(size_t)(bn + n) * K + k0 + lcol]);
            Ws[lcol + 0][n] = v.x; Ws[lcol + 1][n] = v.y;
            Ws[lcol + 2][n] = v.z; Ws[lcol + 3][n] = v.w;
        }
        __syncthreads();
#pragma unroll
        for (int kk = 0; kk < 16; ++kk) {
            float a[8], bb[8];
#pragma unroll
            for (int i = 0; i < 8; ++i) a[i] = Xs[kk][ty * 8 + i];
#pragma unroll
            for (int j = 0; j < 8; ++j) bb[j] = Ws[kk][tx * 8 + j];
#pragma unroll
            for (int i = 0; i < 8; ++i)
#pragma unroll
                for (int j = 0; j < 8; ++j)
                    acc[i][j] = fmaf(a[i], bb[j], acc[i][j]);
        }
        __syncthreads();
    }

#pragma unroll
    for (int i = 0; i < 8; ++i) {
        const int row = bm + ty * 8 + i;
#pragma unroll
        for (int j = 0; j < 8; ++j) {
            const int col = bn + tx * 8 + j;
            if (col < N) {
                float v = acc[i][j];
                if (EPI == 1) v = softplus_f(v + bias[col]);
                Y[(size_t)row * ldy + col] = v;
            }
        }
    }
}

// ---------------- depthwise causal conv (K=4) + SiLU -> g_u ----------------
__global__ __launch_bounds__(256)
void conv_silu_kernel(const float* __restrict__ x, const float* __restrict__ cw)
{
    const int E4 = Ed / 4;
    size_t idx = (size_t)blockIdx.x * blockDim.x + threadIdx.x;
    if (idx >= (size_t)Bd * Ld * E4) return;
    const int e4 = (int)(idx % E4);
    const size_t bl = idx / E4;     // b*L + l
    const int l = (int)(bl % Ld);
    const int e = e4 * 4;
    float a0 = 0.f, a1 = 0.f, a2 = 0.f, a3 = 0.f;
#pragma unroll
    for (int k = 0; k < Kd; ++k) {
        const int ls = l - (Kd - 1) + k;
        if (ls >= 0) {
            const float4 xv = *reinterpret_cast<const float4*>(
                &x[(bl - (Kd - 1) + k) * Ed + e]);
            a0 = fmaf(cw[(e + 0) * Kd + k], xv.x, a0);
            a1 = fmaf(cw[(e + 1) * Kd + k], xv.y, a1);
            a2 = fmaf(cw[(e + 2) * Kd + k], xv.z, a2);
            a3 = fmaf(cw[(e + 3) * Kd + k], xv.w, a3);
        }
    }
    float4 o;
    o.x = silu_f(a0); o.y = silu_f(a1); o.z = silu_f(a2); o.w = silu_f(a3);
    *reinterpret_cast<float4*>(&g_u[bl * Ed + e]) = o;
}

// ---------------- scan phase A: per-chunk local scan (shifted inputs) --------------
// Reference recurrence: h[0] = bt[0]*u[0]; h[t] = a[t-1]*h[t-1] + bt[t-1]*u[t-1].
// So the step at global time t consumes dt/u from index max(t-1, 0).
__global__ __launch_bounds__(256)
void scan_phaseA(const float* __restrict__ A_log)
{
    const int e = blockIdx.x * 256 + threadIdx.x;
    const int c = blockIdx.y, b = blockIdx.z;
    float A[Nd], invA[Nd];
    bool sm[Nd];
#pragma unroll
    for (int n = 0; n < Nd; ++n) {
        A[n] = -expf(A_log[(size_t)e * Nd + n]);
        invA[n] = 1.f / (A[n] + 1e-10f);
        sm[n] = fabsf(A[n]) < 1e-5f;
    }
    float h[Nd], P[Nd];
#pragma unroll
    for (int n = 0; n < Nd; ++n) { h[n] = 0.f; P[n] = 1.f; }
    const size_t base = ((size_t)b * Ld + (size_t)c * CLs) * Ed + e;
    // previous-step values (index c*CLs-1, clamped to c*CLs for chunk 0)
    const size_t pidx = (c > 0) ? (base - Ed) : base;
    float pd = g_dt[pidx];
    float pu = g_u[pidx];
    for (int t = 0; t < CLs; ++t) {
        // recurrence uses the PREVIOUS step's dt/u
#pragma unroll
        for (int n = 0; n < Nd; ++n) {
            const float a = expf(pd * A[n]);
            const float bt = sm[n] ? pd : (a - 1.f) * invA[n];
            h[n] = fmaf(a, h[n], bt * pu);
            P[n] *= a;
        }
        pd = g_dt[base + (size_t)t * Ed];
        pu = g_u[base + (size_t)t * Ed];
    }
    const size_t ho = (((size_t)b * NCH + c) * Ed + e) * Nd;
#pragma unroll
    for (int n = 0; n < Nd; ++n) { g_hend[ho + n] = h[n]; g_P[ho + n] = P[n]; }
}

// ---------------- scan phase B: combine chunk carries (per b,e,n thread) ----------
__global__ __launch_bounds__(256)
void scan_phaseB()
{
    const int gid = blockIdx.x * 256 + threadIdx.x;   // 0 .. B*E*N-1
    const int n = gid & (Nd - 1);
    const int e = (gid >> 4) & (Ed - 1);
    const int b = gid >> 14;
    float h = 0.f;
    size_t idx = (((size_t)b * NCH) * Ed + e) * Nd + n;
    const size_t stride = (size_t)Ed * Nd;
    for (int c = 0; c < NCH; ++c) {
        g_hcarry[idx] = h;
        h = fmaf(g_P[idx], h, g_hend[idx]);
        idx += stride;
    }
}

// ---------------- scan phase C: rescan with carry, compute y, gate -> g_g ----------
__global__ __launch_bounds__(256)
void scan_phaseC(const float* __restrict__ A_log, const float* __restrict__ Dv)
{
    __shared__ float Cs[CLs][Nd];   // 4 KB, broadcast reads
    const int e = blockIdx.x * 256 + threadIdx.x;
    const int c = blockIdx.y, b = blockIdx.z;
    const size_t pbase = ((size_t)b * Ld + (size_t)c * CLs) * Pd;
    for (int i = threadIdx.x; i < CLs * Nd; i += 256) {
        const int t = i >> 4, n = i & 15;
        Cs[t][n] = g_params[pbase + (size_t)t * Pd + (Rd + Nd) + n];
    }
    __syncthreads();

    float A[Nd], invA[Nd];
    bool sm[Nd];
#pragma unroll
    for (int n = 0; n < Nd; ++n) {
        A[n] = -expf(A_log[(size_t)e * Nd + n]);
        invA[n] = 1.f / (A[n] + 1e-10f);
        sm[n] = fabsf(A[n]) < 1e-5f;
    }
    float h[Nd];
    const size_t ho = (((size_t)b * NCH + c) * Ed + e) * Nd;
#pragma unroll
    for (int n = 0; n < Nd; ++n) h[n] = g_hcarry[ho + n];
    const float dve = Dv[e];

    const size_t base = ((size_t)b * Ld + (size_t)c * CLs) * Ed + e;
    // previous-step values for the shifted recurrence
    const size_t pidx = (c > 0) ? (base - Ed) : base;
    float pd = g_dt[pidx];
    float pu = g_u[pidx];
    for (int t = 0; t < CLs; ++t) {
        // recurrence uses PREVIOUS step's dt/u
#pragma unroll
        for (int n = 0; n < Nd; ++n) {
            const float a = expf(pd * A[n]);
            const float bt = sm[n] ? pd : (a - 1.f) * invA[n];
            h[n] = fmaf(a, h[n], bt * pu);
        }
        // output terms use CURRENT step's values
        const float d_cur = g_dt[base + (size_t)t * Ed];
        const float u_cur = g_u[base + (size_t)t * Ed];
        const float z_cur = g_z[base + (size_t)t * Ed];
        float y = 0.f;
#pragma unroll
        for (int n = 0; n < Nd; ++n)
            y = fmaf(Cs[t][n], h[n], y);
        const float ys = fmaf(u_cur, dve, y);
        g_g[base + (size_t)t * Ed] = ys * silu_f(z_cur);
        pd = d_cur;
        pu = u_cur;
    }
}

// ---------------- host launcher ----------------
extern "C" void kernel_launch(void* const* d_in, const int* in_sizes, int n_in,
                              void* d_out, int out_size)
{
    const float* x     = (const float*)d_in[0];
    const float* W_z   = (const float*)d_in[1];
    const float* W_p   = (const float*)d_in[2];
    const float* cw    = (const float*)d_in[3];
    const float* W_dt  = (const float*)d_in[4];
    const float* b_dt  = (const float*)d_in[5];
    const float* A_log = (const float*)d_in[6];
    const float* Dv    = (const float*)d_in[7];
    const float* W_o   = (const float*)d_in[8];
    float* out = (float*)d_out;

    float *z, *params, *dt, *g;
    cudaGetSymbolAddress((void**)&z,      g_z);
    cudaGetSymbolAddress((void**)&params, g_params);
    cudaGetSymbolAddress((void**)&dt,     g_dt);
    cudaGetSymbolAddress((void**)&g,      g_g);

    const int M = Bd * Ld;   // 4096 tokens
    dim3 blk(256);

    // z = x @ W_z^T                         (4096 x 1024, K=1024)
    sgemm_nt<0><<<dim3(Ed / 128, M / 128), blk>>>(x, Ed, W_z, z, Ed, M, Ed, Ed, nullptr);
    // params = x @ W_params^T               (4096 x 96,   K=1024)
    sgemm_nt<0><<<dim3(1, M / 128), blk>>>(x, Ed, W_p, params, Pd, M, Pd, Ed, nullptr);
    // dt = softplus(params[:, :64] @ W_dt^T + b_dt)   (4096 x 1024, K=64)
    sgemm_nt<1><<<dim3(Ed / 128, M / 128), blk>>>(params, Pd, W_dt, dt, Ed, M, Ed, Rd, b_dt);
    // u = silu(causal depthwise conv(x))
    conv_silu_kernel<<<(Bd * Ld * (Ed / 4) + 255) / 256, blk>>>(x, cw);
    // chunked scan (with reference's one-step-delayed recurrence)
    scan_phaseA<<<dim3(Ed / 256, NCH, Bd), blk>>>(A_log);
    scan_phaseB<<<(Bd * Ed * Nd) / 256, blk>>>();
    scan_phaseC<<<dim3(Ed / 256, NCH, Bd), blk>>>(A_log, Dv);
    // out = g @ W_out^T                     (4096 x 1024, K=1024)
    sgemm_nt<0><<<dim3(Ed / 128, M / 128), blk>>>(g, Ed, W_o, out, Ed, M, Ed, Ed, nullptr);
}

// round 5
// speedup vs baseline: 1.7105x; 1.7105x over previous
#include <cuda_runtime.h>
#include <cuda_bf16.h>
#include <math.h>
#include <stdint.h>

// Problem constants
#define Ed 1024
#define Nd 16
#define Kd 4
#define Rd 64
#define Bd 2
#define Ld 2048
#define Pd 96          // R + 2N
#define CLs 64         // chunk length for scan
#define NCH 32         // L / CLs
#define Md (Bd * Ld)   // 4096 tokens

// ---------------- scratch (static device memory; no allocation) ----------------
__device__ __align__(128) float g_z[(size_t)Bd * Ld * Ed];
__device__ __align__(128) float g_params[(size_t)Bd * Ld * Pd];
__device__ __align__(128) float g_dt[(size_t)Bd * Ld * Ed];
__device__ __align__(128) float g_u[(size_t)Bd * Ld * Ed];
__device__ __align__(128) float g_g[(size_t)Bd * Ld * Ed];
__device__ __align__(128) float g_hend[(size_t)Bd * NCH * Ed * Nd];
__device__ __align__(128) float g_P[(size_t)Bd * NCH * Ed * Nd];
__device__ __align__(128) float g_hcarry[(size_t)Bd * NCH * Ed * Nd];

// bf16 hi/lo split planes
__device__ __align__(128) __nv_bfloat16 s_xh[(size_t)Md * Ed];
__device__ __align__(128) __nv_bfloat16 s_xl[(size_t)Md * Ed];
__device__ __align__(128) __nv_bfloat16 s_gh[(size_t)Md * Ed];
__device__ __align__(128) __nv_bfloat16 s_gl[(size_t)Md * Ed];
__device__ __align__(128) __nv_bfloat16 s_ph[(size_t)Md * Pd];
__device__ __align__(128) __nv_bfloat16 s_pl[(size_t)Md * Pd];
__device__ __align__(128) __nv_bfloat16 s_wzh[(size_t)Ed * Ed];
__device__ __align__(128) __nv_bfloat16 s_wzl[(size_t)Ed * Ed];
__device__ __align__(128) __nv_bfloat16 s_wph[(size_t)Pd * Ed];
__device__ __align__(128) __nv_bfloat16 s_wpl[(size_t)Pd * Ed];
__device__ __align__(128) __nv_bfloat16 s_wdh[(size_t)Ed * Rd];
__device__ __align__(128) __nv_bfloat16 s_wdl[(size_t)Ed * Rd];
__device__ __align__(128) __nv_bfloat16 s_woh[(size_t)Ed * Ed];
__device__ __align__(128) __nv_bfloat16 s_wol[(size_t)Ed * Ed];

__device__ __forceinline__ float softplus_f(float v) {
    return v > 20.f ? v : log1pf(expf(v));
}
__device__ __forceinline__ float silu_f(float v) {
    return v / (1.f + expf(-v));
}
// expm1 for small negative y (dt*A in [-0.03, 0] in practice); guarded fallback.
__device__ __forceinline__ float expm1_small(float y) {
    if (y > -0.0625f) {
        return y * (1.f + y * (0.5f + y * (0.16666667f + y * 0.041666667f)));
    }
    return expf(y) - 1.f;
}

// ---------------- fp32 -> bf16 hi/lo split ----------------
__global__ __launch_bounds__(256)
void split_bf16_kernel(const float* __restrict__ in,
                       __nv_bfloat16* __restrict__ hi,
                       __nv_bfloat16* __restrict__ lo, int n4)
{
    int i = blockIdx.x * 256 + threadIdx.x;
    if (i >= n4) return;
    const float4 v = reinterpret_cast<const float4*>(in)[i];
    __nv_bfloat16 h0 = __float2bfloat16(v.x);
    __nv_bfloat16 h1 = __float2bfloat16(v.y);
    __nv_bfloat16 h2 = __float2bfloat16(v.z);
    __nv_bfloat16 h3 = __float2bfloat16(v.w);
    __nv_bfloat162 hh0, hh1, ll0, ll1;
    hh0.x = h0; hh0.y = h1; hh1.x = h2; hh1.y = h3;
    ll0.x = __float2bfloat16(v.x - __bfloat162float(h0));
    ll0.y = __float2bfloat16(v.y - __bfloat162float(h1));
    ll1.x = __float2bfloat16(v.z - __bfloat162float(h2));
    ll1.y = __float2bfloat16(v.w - __bfloat162float(h3));
    reinterpret_cast<__nv_bfloat162*>(hi)[i * 2 + 0] = hh0;
    reinterpret_cast<__nv_bfloat162*>(hi)[i * 2 + 1] = hh1;
    reinterpret_cast<__nv_bfloat162*>(lo)[i * 2 + 0] = ll0;
    reinterpret_cast<__nv_bfloat162*>(lo)[i * 2 + 1] = ll1;
}

// ================= bf16x3 mma.sync GEMM: Y[M,ncols] = A[M,K] @ W[N,K]^T =============
// A = Ah + Al, W = Bh + Bl (planar bf16). Y ~= Ah*Bh + Ah*Bl + Al*Bh (fp32 accum).
// Block 128x128, K-chunk 32, 8 warps (2x4), warp tile 64x32, mma m16n8k16.

#define TSTR 40                       // smem row stride in bf16 (pad 32 -> 40)
#define PLANE (128 * TSTR * 2)        // bytes per plane (10240)
#define STAGE (4 * PLANE)             // Ah,Al,Bh,Bl
#define GSM_TOTAL (2 * STAGE)         // 81920 B

__device__ __forceinline__ void cp16(uint32_t sdst, const void* gsrc, int nbytes) {
    asm volatile("cp.async.cg.shared.global [%0], [%1], 16, %2;"
                 :: "r"(sdst), "l"(gsrc), "r"(nbytes));
}
__device__ __forceinline__ void ldm_x4(uint32_t a, uint32_t& r0, uint32_t& r1,
                                       uint32_t& r2, uint32_t& r3) {
    asm volatile("ldmatrix.sync.aligned.m8n8.x4.shared.b16 {%0,%1,%2,%3}, [%4];"
                 : "=r"(r0), "=r"(r1), "=r"(r2), "=r"(r3) : "r"(a));
}
__device__ __forceinline__ void ldm_x2(uint32_t a, uint32_t& r0, uint32_t& r1) {
    asm volatile("ldmatrix.sync.aligned.m8n8.x2.shared.b16 {%0,%1}, [%2];"
                 : "=r"(r0), "=r"(r1) : "r"(a));
}
__device__ __forceinline__ void mma_bf16(float* d, const uint32_t* a, const uint32_t* b) {
    asm volatile(
        "mma.sync.aligned.m16n8k16.row.col.f32.bf16.bf16.f32 "
        "{%0,%1,%2,%3}, {%4,%5,%6,%7}, {%8,%9}, {%0,%1,%2,%3};"
        : "+f"(d[0]), "+f"(d[1]), "+f"(d[2]), "+f"(d[3])
        : "r"(a[0]), "r"(a[1]), "r"(a[2]), "r"(a[3]), "r"(b[0]), "r"(b[1]));
}

// load one 128x32 bf16 tile (row guard via zfill) into smem plane
__device__ __forceinline__ void load_plane(uint32_t sdst, const __nv_bfloat16* src,
                                           int ld, int row0, int k0, int rows_valid)
{
    const int tid = threadIdx.x;
#pragma unroll
    for (int it = 0; it < 2; ++it) {
        const int slot = tid + it * 256;      // 0..511
        const int row = slot >> 2;            // 0..127
        const int kg = slot & 3;
        const int rv = (row < rows_valid);
        const int r = rv ? row : 0;
        cp16(sdst + (uint32_t)(row * TSTR + kg * 8) * 2,
             src + (size_t)(row0 + r) * ld + k0 + kg * 8,
             rv ? 16 : 0);
    }
}

template <int EPI>
__global__ __launch_bounds__(256)
void gemm_bf16x3(const __nv_bfloat16* __restrict__ Ah,
                 const __nv_bfloat16* __restrict__ Al, int lda,
                 const __nv_bfloat16* __restrict__ Bh,
                 const __nv_bfloat16* __restrict__ Bl, int ldb, int nbrows,
                 float* __restrict__ Y, int ldy, int ncols, int Ktot,
                 const float* __restrict__ bias)
{
    extern __shared__ char smem[];
    const uint32_t sb = (uint32_t)__cvta_generic_to_shared(smem);
    const int tid = threadIdx.x, wid = tid >> 5, lane = tid & 31;
    const int wm = wid & 1, wn = wid >> 1;          // 2 x 4 warp grid
    const int bm = blockIdx.y * 128, bn = blockIdx.x * 128;
    const int nvalid = max(0, min(128, nbrows - bn));

    float acc[4][4][4];
#pragma unroll
    for (int i = 0; i < 4; ++i)
#pragma unroll
        for (int j = 0; j < 4; ++j)
#pragma unroll
            for (int k = 0; k < 4; ++k) acc[i][j][k] = 0.f;

    const int NKT = Ktot >> 5;

    // prologue: stage 0
    load_plane(sb + 0 * PLANE, Ah, lda, bm, 0, 128);
    load_plane(sb + 1 * PLANE, Al, lda, bm, 0, 128);
    load_plane(sb + 2 * PLANE, Bh, ldb, bn, 0, nvalid);
    load_plane(sb + 3 * PLANE, Bl, ldb, bn, 0, nvalid);
    asm volatile("cp.async.commit_group;" ::: "memory");
    asm volatile("cp.async.wait_group 0;" ::: "memory");
    __syncthreads();

    const int lr = lane & 7;
    const int ag1 = (lane >> 3) & 1;   // A row block
    const int ag2 = (lane >> 4) & 1;   // A col block
    const int bg1 = (lane >> 3) & 1;   // B k block (lanes 0..15 used)

    for (int kt = 0; kt < NKT; ++kt) {
        const uint32_t st = sb + (uint32_t)(kt & 1) * STAGE;
        if (kt + 1 < NKT) {
            const uint32_t st2 = sb + (uint32_t)((kt + 1) & 1) * STAGE;
            const int k0 = (kt + 1) << 5;
            load_plane(st2 + 0 * PLANE, Ah, lda, bm, k0, 128);
            load_plane(st2 + 1 * PLANE, Al, lda, bm, k0, 128);
            load_plane(st2 + 2 * PLANE, Bh, ldb, bn, k0, nvalid);
            load_plane(st2 + 3 * PLANE, Bl, ldb, bn, k0, nvalid);
            asm volatile("cp.async.commit_group;" ::: "memory");
        }
#pragma unroll
        for (int ks = 0; ks < 2; ++ks) {
            uint32_t ah[4][4], al[4][4], bh[4][2], bl[4][2];
#pragma unroll
            for (int mi = 0; mi < 4; ++mi) {
                const uint32_t off = (uint32_t)((wm * 64 + mi * 16 + ag1 * 8 + lr) * TSTR
                                                + ks * 16 + ag2 * 8) * 2;
                ldm_x4(st + 0 * PLANE + off, ah[mi][0], ah[mi][1], ah[mi][2], ah[mi][3]);
                ldm_x4(st + 1 * PLANE + off, al[mi][0], al[mi][1], al[mi][2], al[mi][3]);
            }
#pragma unroll
            for (int ni = 0; ni < 4; ++ni) {
                const uint32_t off = (uint32_t)((wn * 32 + ni * 8 + lr) * TSTR
                                                + ks * 16 + bg1 * 8) * 2;
                ldm_x2(st + 2 * PLANE + off, bh[ni][0], bh[ni][1]);
                ldm_x2(st + 3 * PLANE + off, bl[ni][0], bl[ni][1]);
            }
#pragma unroll
            for (int mi = 0; mi < 4; ++mi)
#pragma unroll
                for (int ni = 0; ni < 4; ++ni) {
                    mma_bf16(acc[mi][ni], ah[mi], bh[ni]);
                    mma_bf16(acc[mi][ni], ah[mi], bl[ni]);
                    mma_bf16(acc[mi][ni], al[mi], bh[ni]);
                }
        }
        asm volatile("cp.async.wait_group 0;" ::: "memory");
        __syncthreads();
    }

    // epilogue: write accumulators
#pragma unroll
    for (int mi = 0; mi < 4; ++mi) {
        const int row = bm + wm * 64 + mi * 16 + (lane >> 2);
#pragma unroll
        for (int ni = 0; ni < 4; ++ni) {
            const int col = bn + wn * 32 + ni * 8 + (lane & 3) * 2;
            if (col >= ncols) continue;
            float2 v01 = make_float2(acc[mi][ni][0], acc[mi][ni][1]);
            float2 v23 = make_float2(acc[mi][ni][2], acc[mi][ni][3]);
            if (EPI == 1) {
                const float b0 = bias[col], b1 = bias[col + 1];
                v01.x = softplus_f(v01.x + b0); v01.y = softplus_f(v01.y + b1);
                v23.x = softplus_f(v23.x + b0); v23.y = softplus_f(v23.y + b1);
            }
            *reinterpret_cast<float2*>(&Y[(size_t)row * ldy + col]) = v01;
            *reinterpret_cast<float2*>(&Y[(size_t)(row + 8) * ldy + col]) = v23;
        }
    }
}

// ---------------- depthwise causal conv (K=4) + SiLU -> g_u ----------------
__global__ __launch_bounds__(256)
void conv_silu_kernel(const float* __restrict__ x, const float* __restrict__ cw)
{
    const int E4 = Ed / 4;
    size_t idx = (size_t)blockIdx.x * blockDim.x + threadIdx.x;
    if (idx >= (size_t)Bd * Ld * E4) return;
    const int e4 = (int)(idx % E4);
    const size_t bl = idx / E4;     // b*L + l
    const int l = (int)(bl % Ld);
    const int e = e4 * 4;
    float a0 = 0.f, a1 = 0.f, a2 = 0.f, a3 = 0.f;
#pragma unroll
    for (int k = 0; k < Kd; ++k) {
        const int ls = l - (Kd - 1) + k;
        if (ls >= 0) {
            const float4 xv = *reinterpret_cast<const float4*>(
                &x[(bl - (Kd - 1) + k) * Ed + e]);
            a0 = fmaf(cw[(e + 0) * Kd + k], xv.x, a0);
            a1 = fmaf(cw[(e + 1) * Kd + k], xv.y, a1);
            a2 = fmaf(cw[(e + 2) * Kd + k], xv.z, a2);
            a3 = fmaf(cw[(e + 3) * Kd + k], xv.w, a3);
        }
    }
    float4 o;
    o.x = silu_f(a0); o.y = silu_f(a1); o.z = silu_f(a2); o.w = silu_f(a3);
    *reinterpret_cast<float4*>(&g_u[bl * Ed + e]) = o;
}

// ---------------- scan phase A: per-chunk local scan (shifted inputs) --------------
// Reference recurrence: h[0] = bt[0]*u[0]; h[t] = a[t-1]*h[t-1] + bt[t-1]*u[t-1].
__global__ __launch_bounds__(256)
void scan_phaseA(const float* __restrict__ A_log)
{
    const int e = blockIdx.x * 256 + threadIdx.x;
    const int c = blockIdx.y, b = blockIdx.z;
    float A[Nd], invA[Nd];
    bool sm[Nd];
#pragma unroll
    for (int n = 0; n < Nd; ++n) {
        A[n] = -expf(A_log[(size_t)e * Nd + n]);
        invA[n] = 1.f / (A[n] + 1e-10f);
        sm[n] = fabsf(A[n]) < 1e-5f;
    }
    float h[Nd], P[Nd];
#pragma unroll
    for (int n = 0; n < Nd; ++n) { h[n] = 0.f; P[n] = 1.f; }
    const size_t base = ((size_t)b * Ld + (size_t)c * CLs) * Ed + e;
    const size_t pidx = (c > 0) ? (base - Ed) : base;
    float pd = g_dt[pidx];
    float pu = g_u[pidx];
    for (int t = 0; t < CLs; ++t) {
#pragma unroll
        for (int n = 0; n < Nd; ++n) {
            const float em1 = expm1_small(pd * A[n]);
            const float a = 1.f + em1;
            const float bt = sm[n] ? pd : em1 * invA[n];
            h[n] = fmaf(a, h[n], bt * pu);
            P[n] *= a;
        }
        pd = g_dt[base + (size_t)t * Ed];
        pu = g_u[base + (size_t)t * Ed];
    }
    const size_t ho = (((size_t)b * NCH + c) * Ed + e) * Nd;
#pragma unroll
    for (int n = 0; n < Nd; ++n) { g_hend[ho + n] = h[n]; g_P[ho + n] = P[n]; }
}

// ---------------- scan phase B: combine chunk carries (per b,e,n thread) ----------
__global__ __launch_bounds__(256)
void scan_phaseB()
{
    const int gid = blockIdx.x * 256 + threadIdx.x;   // 0 .. B*E*N-1
    const int n = gid & (Nd - 1);
    const int e = (gid >> 4) & (Ed - 1);
    const int b = gid >> 14;
    float h = 0.f;
    size_t idx = (((size_t)b * NCH) * Ed + e) * Nd + n;
    const size_t stride = (size_t)Ed * Nd;
    for (int c = 0; c < NCH; ++c) {
        g_hcarry[idx] = h;
        h = fmaf(g_P[idx], h, g_hend[idx]);
        idx += stride;
    }
}

// ---------------- scan phase C: rescan with carry, compute y, gate -> g_g ----------
__global__ __launch_bounds__(256)
void scan_phaseC(const float* __restrict__ A_log, const float* __restrict__ Dv)
{
    __shared__ float Cs[CLs][Nd];   // 4 KB, broadcast reads
    const int e = blockIdx.x * 256 + threadIdx.x;
    const int c = blockIdx.y, b = blockIdx.z;
    const size_t pbase = ((size_t)b * Ld + (size_t)c * CLs) * Pd;
    for (int i = threadIdx.x; i < CLs * Nd; i += 256) {
        const int t = i >> 4, n = i & 15;
        Cs[t][n] = g_params[pbase + (size_t)t * Pd + (Rd + Nd) + n];
    }
    __syncthreads();

    float A[Nd], invA[Nd];
    bool sm[Nd];
#pragma unroll
    for (int n = 0; n < Nd; ++n) {
        A[n] = -expf(A_log[(size_t)e * Nd + n]);
        invA[n] = 1.f / (A[n] + 1e-10f);
        sm[n] = fabsf(A[n]) < 1e-5f;
    }
    float h[Nd];
    const size_t ho = (((size_t)b * NCH + c) * Ed + e) * Nd;
#pragma unroll
    for (int n = 0; n < Nd; ++n) h[n] = g_hcarry[ho + n];
    const float dve = Dv[e];

    const size_t base = ((size_t)b * Ld + (size_t)c * CLs) * Ed + e;
    const size_t pidx = (c > 0) ? (base - Ed) : base;
    float pd = g_dt[pidx];
    float pu = g_u[pidx];
    for (int t = 0; t < CLs; ++t) {
#pragma unroll
        for (int n = 0; n < Nd; ++n) {
            const float em1 = expm1_small(pd * A[n]);
            const float a = 1.f + em1;
            const float bt = sm[n] ? pd : em1 * invA[n];
            h[n] = fmaf(a, h[n], bt * pu);
        }
        const float d_cur = g_dt[base + (size_t)t * Ed];
        const float u_cur = g_u[base + (size_t)t * Ed];
        const float z_cur = g_z[base + (size_t)t * Ed];
        float y = 0.f;
#pragma unroll
        for (int n = 0; n < Nd; ++n)
            y = fmaf(Cs[t][n], h[n], y);
        const float ys = fmaf(u_cur, dve, y);
        g_g[base + (size_t)t * Ed] = ys * silu_f(z_cur);
        pd = d_cur;
        pu = u_cur;
    }
}

// ---------------- host launcher ----------------
extern "C" void kernel_launch(void* const* d_in, const int* in_sizes, int n_in,
                              void* d_out, int out_size)
{
    const float* x     = (const float*)d_in[0];
    const float* W_z   = (const float*)d_in[1];
    const float* W_p   = (const float*)d_in[2];
    const float* cw    = (const float*)d_in[3];
    const float* W_dt  = (const float*)d_in[4];
    const float* b_dt  = (const float*)d_in[5];
    const float* A_log = (const float*)d_in[6];
    const float* Dv    = (const float*)d_in[7];
    const float* W_o   = (const float*)d_in[8];
    float* out = (float*)d_out;

    float *z, *params, *dt, *g;
    cudaGetSymbolAddress((void**)&z,      g_z);
    cudaGetSymbolAddress((void**)&params, g_params);
    cudaGetSymbolAddress((void**)&dt,     g_dt);
    cudaGetSymbolAddress((void**)&g,      g_g);

    __nv_bfloat16 *xh, *xl, *gh, *gl, *ph, *pl;
    __nv_bfloat16 *wzh, *wzl, *wph, *wpl, *wdh, *wdl, *woh, *wol;
    cudaGetSymbolAddress((void**)&xh, s_xh);   cudaGetSymbolAddress((void**)&xl, s_xl);
    cudaGetSymbolAddress((void**)&gh, s_gh);   cudaGetSymbolAddress((void**)&gl, s_gl);
    cudaGetSymbolAddress((void**)&ph, s_ph);   cudaGetSymbolAddress((void**)&pl, s_pl);
    cudaGetSymbolAddress((void**)&wzh, s_wzh); cudaGetSymbolAddress((void**)&wzl, s_wzl);
    cudaGetSymbolAddress((void**)&wph, s_wph); cudaGetSymbolAddress((void**)&wpl, s_wpl);
    cudaGetSymbolAddress((void**)&wdh, s_wdh); cudaGetSymbolAddress((void**)&wdl, s_wdl);
    cudaGetSymbolAddress((void**)&woh, s_wol ? s_woh : s_woh); cudaGetSymbolAddress((void**)&wol, s_wol);

    cudaFuncSetAttribute(gemm_bf16x3<0>, cudaFuncAttributeMaxDynamicSharedMemorySize, GSM_TOTAL);
    cudaFuncSetAttribute(gemm_bf16x3<1>, cudaFuncAttributeMaxDynamicSharedMemorySize, GSM_TOTAL);

    dim3 blk(256);
    auto spl = [&](const float* src, __nv_bfloat16* h, __nv_bfloat16* l, int n) {
        split_bf16_kernel<<<(n / 4 + 255) / 256, blk>>>(src, h, l, n / 4);
    };

    // input splits
    spl(x,    xh,  xl,  Md * Ed);
    spl(W_z,  wzh, wzl, Ed * Ed);
    spl(W_p,  wph, wpl, Pd * Ed);
    spl(W_dt, wdh, wdl, Ed * Rd);
    spl(W_o,  woh, wol, Ed * Ed);

    // z = x @ W_z^T                          (4096 x 1024, K=1024)
    gemm_bf16x3<0><<<dim3(Ed / 128, Md / 128), blk, GSM_TOTAL>>>(
        xh, xl, Ed, wzh, wzl, Ed, Ed, z, Ed, Ed, Ed, nullptr);
    // params = x @ W_params^T                (4096 x 96,   K=1024)
    gemm_bf16x3<0><<<dim3(1, Md / 128), blk, GSM_TOTAL>>>(
        xh, xl, Ed, wph, wpl, Ed, Pd, params, Pd, Pd, Ed, nullptr);
    // split params for dt gemm
    spl(params, ph, pl, Md * Pd);
    // dt = softplus(params[:, :64] @ W_dt^T + b_dt)   (4096 x 1024, K=64)
    gemm_bf16x3<1><<<dim3(Ed / 128, Md / 128), blk, GSM_TOTAL>>>(
        ph, pl, Pd, wdh, wdl, Rd, Ed, dt, Ed, Ed, Rd, b_dt);
    // u = silu(causal depthwise conv(x))
    conv_silu_kernel<<<(Bd * Ld * (Ed / 4) + 255) / 256, blk>>>(x, cw);
    // chunked scan (reference's one-step-delayed recurrence)
    scan_phaseA<<<dim3(Ed / 256, NCH, Bd), blk>>>(A_log);
    scan_phaseB<<<(Bd * Ed * Nd) / 256, blk>>>();
    scan_phaseC<<<dim3(Ed / 256, NCH, Bd), blk>>>(A_log, Dv);
    // out = g @ W_out^T                      (4096 x 1024, K=1024)
    spl(g, gh, gl, Md * Ed);
    gemm_bf16x3<0><<<dim3(Ed / 128, Md / 128), blk, GSM_TOTAL>>>(
        gh, gl, Ed, woh, wol, Ed, Ed, out, Ed, Ed, Ed, nullptr);
}

// round 6
// speedup vs baseline: 2.7210x; 1.5908x over previous
#include <cuda_runtime.h>
#include <cuda_fp16.h>
#include <math.h>
#include <stdint.h>

// Problem constants
#define Ed 1024
#define Nd 16
#define Kd 4
#define Rd 64
#define Bd 2
#define Ld 2048
#define Pd 96          // R + 2N
#define CLs 64         // chunk length for scan
#define NCH 32         // L / CLs
#define Md (Bd * Ld)   // 4096 tokens

// ---------------- scratch (static device memory; no allocation) ----------------
__device__ __align__(128) float g_z[(size_t)Md * Ed];
__device__ __align__(128) float g_params[(size_t)Md * Pd];
__device__ __align__(128) float g_dt[(size_t)Md * Ed];
__device__ __align__(128) float g_u[(size_t)Md * Ed];
__device__ __align__(128) float g_hend[(size_t)Bd * NCH * Ed * Nd];
__device__ __align__(128) float g_P[(size_t)Bd * NCH * Ed * Nd];
__device__ __align__(128) float g_hcarry[(size_t)Bd * NCH * Ed * Nd];

// fp16 activation planes (A side, hi only) and weight hi/lo splits
__device__ __align__(128) __half s_xh[(size_t)Md * Ed];
__device__ __align__(128) __half s_gh[(size_t)Md * Ed];
__device__ __align__(128) __half s_ph[(size_t)Md * Pd];
__device__ __align__(128) __half s_wzh[(size_t)Ed * Ed];
__device__ __align__(128) __half s_wzl[(size_t)Ed * Ed];
__device__ __align__(128) __half s_wph[(size_t)Pd * Ed];
__device__ __align__(128) __half s_wpl[(size_t)Pd * Ed];
__device__ __align__(128) __half s_wdh[(size_t)Ed * Rd];
__device__ __align__(128) __half s_wdl[(size_t)Ed * Rd];
__device__ __align__(128) __half s_woh[(size_t)Ed * Ed];
__device__ __align__(128) __half s_wol[(size_t)Ed * Ed];

__device__ __forceinline__ float softplus_f(float v) {
    return v > 20.f ? v : log1pf(expf(v));
}
__device__ __forceinline__ float silu_f(float v) {
    return v / (1.f + expf(-v));
}
// expm1 for small negative y (dt*A in [-0.03, 0] in practice); guarded fallback.
__device__ __forceinline__ float expm1_small(float y) {
    if (y > -0.0625f) {
        return y * (1.f + y * (0.5f + y * (0.16666667f + y * 0.041666667f)));
    }
    return expf(y) - 1.f;
}

// ---------------- fp32 -> fp16 cast / hi-lo split ----------------
__global__ __launch_bounds__(256)
void cast_half_kernel(const float* __restrict__ in, __half* __restrict__ out, int n4)
{
    int i = blockIdx.x * 256 + threadIdx.x;
    if (i >= n4) return;
    const float4 v = reinterpret_cast<const float4*>(in)[i];
    reinterpret_cast<__half2*>(out)[i * 2 + 0] = __floats2half2_rn(v.x, v.y);
    reinterpret_cast<__half2*>(out)[i * 2 + 1] = __floats2half2_rn(v.z, v.w);
}
__global__ __launch_bounds__(256)
void split_half_kernel(const float* __restrict__ in,
                       __half* __restrict__ hi, __half* __restrict__ lo, int n4)
{
    int i = blockIdx.x * 256 + threadIdx.x;
    if (i >= n4) return;
    const float4 v = reinterpret_cast<const float4*>(in)[i];
    __half h0 = __float2half_rn(v.x), h1 = __float2half_rn(v.y);
    __half h2 = __float2half_rn(v.z), h3 = __float2half_rn(v.w);
    __half2 hh0; hh0.x = h0; hh0.y = h1;
    __half2 hh1; hh1.x = h2; hh1.y = h3;
    __half2 ll0, ll1;
    ll0.x = __float2half_rn(v.x - __half2float(h0));
    ll0.y = __float2half_rn(v.y - __half2float(h1));
    ll1.x = __float2half_rn(v.z - __half2float(h2));
    ll1.y = __float2half_rn(v.w - __half2float(h3));
    reinterpret_cast<__half2*>(hi)[i * 2 + 0] = hh0;
    reinterpret_cast<__half2*>(hi)[i * 2 + 1] = hh1;
    reinterpret_cast<__half2*>(lo)[i * 2 + 0] = ll0;
    reinterpret_cast<__half2*>(lo)[i * 2 + 1] = ll1;
}

// ================= fp16 2-term compensated GEMM =================
// Y[M,n] = A[M,K] @ (Wh + Wl)[N,K]^T ; A plain fp16, W split hi/lo.
// Block 128x128, K-chunk 64, 8 warps (2x4), warp tile 64x32, mma m16n8k16.

#define TSTR2 72                       // smem row stride in fp16 (64 -> 72; 144B, 16B-mult)
#define PLN (128 * TSTR2 * 2)          // 18432 B per plane
#define STG (3 * PLN)                  // A, Bh, Bl = 55296 B
#define GSM (2 * STG)                  // 110592 B

__device__ __forceinline__ void cp16(uint32_t sdst, const void* gsrc, int nbytes) {
    asm volatile("cp.async.cg.shared.global [%0], [%1], 16, %2;"
                 :: "r"(sdst), "l"(gsrc), "r"(nbytes));
}
__device__ __forceinline__ void ldm_x4(uint32_t a, uint32_t& r0, uint32_t& r1,
                                       uint32_t& r2, uint32_t& r3) {
    asm volatile("ldmatrix.sync.aligned.m8n8.x4.shared.b16 {%0,%1,%2,%3}, [%4];"
                 : "=r"(r0), "=r"(r1), "=r"(r2), "=r"(r3) : "r"(a));
}
__device__ __forceinline__ void ldm_x2(uint32_t a, uint32_t& r0, uint32_t& r1) {
    asm volatile("ldmatrix.sync.aligned.m8n8.x2.shared.b16 {%0,%1}, [%2];"
                 : "=r"(r0), "=r"(r1) : "r"(a));
}
__device__ __forceinline__ void mma_f16(float* d, const uint32_t* a, const uint32_t* b) {
    asm volatile(
        "mma.sync.aligned.m16n8k16.row.col.f32.f16.f16.f32 "
        "{%0,%1,%2,%3}, {%4,%5,%6,%7}, {%8,%9}, {%0,%1,%2,%3};"
        : "+f"(d[0]), "+f"(d[1]), "+f"(d[2]), "+f"(d[3])
        : "r"(a[0]), "r"(a[1]), "r"(a[2]), "r"(a[3]), "r"(b[0]), "r"(b[1]));
}

// load one 128x64 fp16 tile (row zfill guard) into an smem plane
__device__ __forceinline__ void ldp64(uint32_t sdst, const __half* src, int ld,
                                      int row0, int k0, int rows_valid)
{
    const int tid = threadIdx.x;
#pragma unroll
    for (int it = 0; it < 4; ++it) {
        const int slot = tid + (it << 8);     // 0..1023
        const int row = slot >> 3;            // 0..127
        const int kg = slot & 7;              // 0..7 (8 halves each)
        const int rv = (row < rows_valid);
        cp16(sdst + (uint32_t)(row * TSTR2 + kg * 8) * 2,
             src + (size_t)(row0 + (rv ? row : 0)) * ld + k0 + kg * 8,
             rv ? 16 : 0);
    }
}

__device__ __forceinline__ void gemm_core(
    uint32_t sb, const __half* __restrict__ Ah, int lda,
    const __half* __restrict__ Bh, const __half* __restrict__ Bl,
    int ldb, int nvB, int Ktot, int bm, int bn, float acc[4][4][4])
{
    const int tid = threadIdx.x, wid = tid >> 5, lane = tid & 31;
    const int wm = wid & 1, wn = wid >> 1;
    const int NKT = Ktot >> 6;

    ldp64(sb + 0 * PLN, Ah, lda, bm, 0, 128);
    ldp64(sb + 1 * PLN, Bh, ldb, bn, 0, nvB);
    ldp64(sb + 2 * PLN, Bl, ldb, bn, 0, nvB);
    asm volatile("cp.async.commit_group;" ::: "memory");
    asm volatile("cp.async.wait_group 0;" ::: "memory");
    __syncthreads();

    const int lr = lane & 7;
    const int ag1 = (lane >> 3) & 1;
    const int ag2 = (lane >> 4) & 1;
    const int bg1 = (lane >> 3) & 1;

    for (int kt = 0; kt < NKT; ++kt) {
        const uint32_t st = sb + (uint32_t)(kt & 1) * STG;
        if (kt + 1 < NKT) {
            const uint32_t st2 = sb + (uint32_t)((kt + 1) & 1) * STG;
            const int k0 = (kt + 1) << 6;
            ldp64(st2 + 0 * PLN, Ah, lda, bm, k0, 128);
            ldp64(st2 + 1 * PLN, Bh, ldb, bn, k0, nvB);
            ldp64(st2 + 2 * PLN, Bl, ldb, bn, k0, nvB);
            asm volatile("cp.async.commit_group;" ::: "memory");
        }
#pragma unroll
        for (int ks = 0; ks < 4; ++ks) {
            uint32_t ah[4][4], bh[4][2], bl[4][2];
#pragma unroll
            for (int mi = 0; mi < 4; ++mi) {
                const uint32_t off = (uint32_t)((wm * 64 + mi * 16 + ag1 * 8 + lr) * TSTR2
                                                + ks * 16 + ag2 * 8) * 2;
                ldm_x4(st + 0 * PLN + off, ah[mi][0], ah[mi][1], ah[mi][2], ah[mi][3]);
            }
#pragma unroll
            for (int ni = 0; ni < 4; ++ni) {
                const uint32_t off = (uint32_t)((wn * 32 + ni * 8 + lr) * TSTR2
                                                + ks * 16 + bg1 * 8) * 2;
                ldm_x2(st + 1 * PLN + off, bh[ni][0], bh[ni][1]);
                ldm_x2(st + 2 * PLN + off, bl[ni][0], bl[ni][1]);
            }
#pragma unroll
            for (int mi = 0; mi < 4; ++mi)
#pragma unroll
                for (int ni = 0; ni < 4; ++ni) {
                    mma_f16(acc[mi][ni], ah[mi], bh[ni]);
                    mma_f16(acc[mi][ni], ah[mi], bl[ni]);
                }
        }
        asm volatile("cp.async.wait_group 0;" ::: "memory");
        __syncthreads();
    }
}

// merged z + params GEMM: bx<8 -> z tile; bx==8 -> params tile (also emits ph fp16)
__global__ __launch_bounds__(256, 2)
void gemm_zp(const __half* __restrict__ xh,
             const __half* __restrict__ wzh, const __half* __restrict__ wzl,
             const __half* __restrict__ wph, const __half* __restrict__ wpl,
             float* __restrict__ z, float* __restrict__ params,
             __half* __restrict__ ph)
{
    extern __shared__ char smem[];
    const uint32_t sb = (uint32_t)__cvta_generic_to_shared(smem);
    const int tid = threadIdx.x, wid = tid >> 5, lane = tid & 31;
    const int wm = wid & 1, wn = wid >> 1;
    const int bx = blockIdx.x, bm = blockIdx.y * 128;

    float acc[4][4][4];
#pragma unroll
    for (int i = 0; i < 4; ++i)
#pragma unroll
        for (int j = 0; j < 4; ++j)
#pragma unroll
            for (int k = 0; k < 4; ++k) acc[i][j][k] = 0.f;

    if (bx < 8) {
        gemm_core(sb, xh, Ed, wzh, wzl, Ed, 128, Ed, bm, bx * 128, acc);
#pragma unroll
        for (int mi = 0; mi < 4; ++mi) {
            const int row = bm + wm * 64 + mi * 16 + (lane >> 2);
#pragma unroll
            for (int ni = 0; ni < 4; ++ni) {
                const int col = bx * 128 + wn * 32 + ni * 8 + (lane & 3) * 2;
                *reinterpret_cast<float2*>(&z[(size_t)row * Ed + col]) =
                    make_float2(acc[mi][ni][0], acc[mi][ni][1]);
                *reinterpret_cast<float2*>(&z[(size_t)(row + 8) * Ed + col]) =
                    make_float2(acc[mi][ni][2], acc[mi][ni][3]);
            }
        }
    } else {
        gemm_core(sb, xh, Ed, wph, wpl, Ed, Pd, Ed, bm, 0, acc);
#pragma unroll
        for (int mi = 0; mi < 4; ++mi) {
            const int r0 = bm + wm * 64 + mi * 16 + (lane >> 2);
#pragma unroll
            for (int ni = 0; ni < 4; ++ni) {
                const int col = wn * 32 + ni * 8 + (lane & 3) * 2;
                if (col >= Pd) continue;
#pragma unroll
                for (int hh = 0; hh < 2; ++hh) {
                    const int row = r0 + hh * 8;
                    const float v0 = acc[mi][ni][hh * 2 + 0];
                    const float v1 = acc[mi][ni][hh * 2 + 1];
                    *reinterpret_cast<float2*>(&params[(size_t)row * Pd + col]) =
                        make_float2(v0, v1);
                    if (col < Rd) {
                        __half2 hv; hv.x = __float2half_rn(v0); hv.y = __float2half_rn(v1);
                        *reinterpret_cast<__half2*>(&ph[(size_t)row * Pd + col]) = hv;
                    }
                }
            }
        }
    }
}

// generic GEMM (full tiles): Y = A @ (Wh+Wl)^T, optional softplus(+bias)
__global__ __launch_bounds__(256, 2)
void gemm_gen(const __half* __restrict__ Ah, int lda,
              const __half* __restrict__ Bh, const __half* __restrict__ Bl, int ldb,
              float* __restrict__ Y, int ldy, int Ktot,
              const float* __restrict__ bias)
{
    extern __shared__ char smem[];
    const uint32_t sb = (uint32_t)__cvta_generic_to_shared(smem);
    const int tid = threadIdx.x, wid = tid >> 5, lane = tid & 31;
    const int wm = wid & 1, wn = wid >> 1;
    const int bm = blockIdx.y * 128, bn = blockIdx.x * 128;

    float acc[4][4][4];
#pragma unroll
    for (int i = 0; i < 4; ++i)
#pragma unroll
        for (int j = 0; j < 4; ++j)
#pragma unroll
            for (int k = 0; k < 4; ++k) acc[i][j][k] = 0.f;

    gemm_core(sb, Ah, lda, Bh, Bl, ldb, 128, Ktot, bm, bn, acc);

#pragma unroll
    for (int mi = 0; mi < 4; ++mi) {
        const int row = bm + wm * 64 + mi * 16 + (lane >> 2);
#pragma unroll
        for (int ni = 0; ni < 4; ++ni) {
            const int col = bn + wn * 32 + ni * 8 + (lane & 3) * 2;
            float2 v01 = make_float2(acc[mi][ni][0], acc[mi][ni][1]);
            float2 v23 = make_float2(acc[mi][ni][2], acc[mi][ni][3]);
            if (bias) {
                const float b0 = bias[col], b1 = bias[col + 1];
                v01.x = softplus_f(v01.x + b0); v01.y = softplus_f(v01.y + b1);
                v23.x = softplus_f(v23.x + b0); v23.y = softplus_f(v23.y + b1);
            }
            *reinterpret_cast<float2*>(&Y[(size_t)row * ldy + col]) = v01;
            *reinterpret_cast<float2*>(&Y[(size_t)(row + 8) * ldy + col]) = v23;
        }
    }
}

// ---------------- depthwise causal conv (K=4) + SiLU -> g_u (4 l per thread) -------
__global__ __launch_bounds__(256)
void conv_silu_kernel(const float* __restrict__ x, const float* __restrict__ cw)
{
    const int idx = blockIdx.x * 256 + threadIdx.x;   // (Md/4)*(Ed/4) = 262144
    const int e4 = idx & 255;
    const int bl4 = idx >> 8;          // 0..1023
    const int b = bl4 >> 9;
    const int l0 = (bl4 & 511) << 2;
    const int e = e4 << 2;
    const size_t rowbase = ((size_t)b * Ld) * Ed + e;

    float4 wc[4];
#pragma unroll
    for (int c = 0; c < 4; ++c)
        wc[c] = *reinterpret_cast<const float4*>(&cw[(size_t)(e + c) * Kd]);

    float4 xr[7];
#pragma unroll
    for (int j = 0; j < 7; ++j) {
        const int l = l0 - 3 + j;
        xr[j] = (l >= 0) ? *reinterpret_cast<const float4*>(&x[rowbase + (size_t)l * Ed])
                         : make_float4(0.f, 0.f, 0.f, 0.f);
    }
#pragma unroll
    for (int i = 0; i < 4; ++i) {
        float a0 = 0.f, a1 = 0.f, a2 = 0.f, a3 = 0.f;
#pragma unroll
        for (int k = 0; k < Kd; ++k) {
            const float4 xv = xr[i + k];
            a0 = fmaf(((const float*)&wc[0])[k], xv.x, a0);
            a1 = fmaf(((const float*)&wc[1])[k], xv.y, a1);
            a2 = fmaf(((const float*)&wc[2])[k], xv.z, a2);
            a3 = fmaf(((const float*)&wc[3])[k], xv.w, a3);
        }
        float4 o;
        o.x = silu_f(a0); o.y = silu_f(a1); o.z = silu_f(a2); o.w = silu_f(a3);
        *reinterpret_cast<float4*>(&g_u[rowbase + (size_t)(l0 + i) * Ed]) = o;
    }
}

// ---------------- scan phase A: per-chunk local scan (shifted inputs) --------------
// Reference recurrence: h[0] = bt[0]*u[0]; h[t] = a[t-1]*h[t-1] + bt[t-1]*u[t-1].
__global__ __launch_bounds__(256)
void scan_phaseA(const float* __restrict__ A_log)
{
    const int e = blockIdx.x * 256 + threadIdx.x;
    const int c = blockIdx.y, b = blockIdx.z;
    float A[Nd], invA[Nd];
    bool sm[Nd];
#pragma unroll
    for (int n = 0; n < Nd; ++n) {
        A[n] = -expf(A_log[(size_t)e * Nd + n]);
        invA[n] = 1.f / (A[n] + 1e-10f);
        sm[n] = fabsf(A[n]) < 1e-5f;
    }
    float h[Nd], P[Nd];
#pragma unroll
    for (int n = 0; n < Nd; ++n) { h[n] = 0.f; P[n] = 1.f; }
    const size_t base = ((size_t)b * Ld + (size_t)c * CLs) * Ed + e;
    const size_t pidx = (c > 0) ? (base - Ed) : base;
    float pd = g_dt[pidx];
    float pu = g_u[pidx];
    for (int t = 0; t < CLs; ++t) {
#pragma unroll
        for (int n = 0; n < Nd; ++n) {
            const float em1 = expm1_small(pd * A[n]);
            const float a = 1.f + em1;
            const float bt = sm[n] ? pd : em1 * invA[n];
            h[n] = fmaf(a, h[n], bt * pu);
            P[n] *= a;
        }
        pd = g_dt[base + (size_t)t * Ed];
        pu = g_u[base + (size_t)t * Ed];
    }
    const size_t ho = (((size_t)b * NCH + c) * Ed + e) * Nd;
#pragma unroll
    for (int n = 0; n < Nd; ++n) { g_hend[ho + n] = h[n]; g_P[ho + n] = P[n]; }
}

// ---------------- scan phase B: combine chunk carries (per b,e,n thread) ----------
__global__ __launch_bounds__(256)
void scan_phaseB()
{
    const int gid = blockIdx.x * 256 + threadIdx.x;   // 0 .. B*E*N-1
    const int n = gid & (Nd - 1);
    const int e = (gid >> 4) & (Ed - 1);
    const int b = gid >> 14;
    float h = 0.f;
    size_t idx = (((size_t)b * NCH) * Ed + e) * Nd + n;
    const size_t stride = (size_t)Ed * Nd;
    for (int c = 0; c < NCH; ++c) {
        g_hcarry[idx] = h;
        h = fmaf(g_P[idx], h, g_hend[idx]);
        idx += stride;
    }
}

// ---------------- scan phase C: rescan with carry, compute y, gate -> gh (fp16) ----
__global__ __launch_bounds__(256)
void scan_phaseC(const float* __restrict__ A_log, const float* __restrict__ Dv)
{
    __shared__ float Cs[CLs][Nd];   // 4 KB, broadcast reads
    const int e = blockIdx.x * 256 + threadIdx.x;
    const int c = blockIdx.y, b = blockIdx.z;
    const size_t pbase = ((size_t)b * Ld + (size_t)c * CLs) * Pd;
    for (int i = threadIdx.x; i < CLs * Nd; i += 256) {
        const int t = i >> 4, n = i & 15;
        Cs[t][n] = g_params[pbase + (size_t)t * Pd + (Rd + Nd) + n];
    }
    __syncthreads();

    float A[Nd], invA[Nd];
    bool sm[Nd];
#pragma unroll
    for (int n = 0; n < Nd; ++n) {
        A[n] = -expf(A_log[(size_t)e * Nd + n]);
        invA[n] = 1.f / (A[n] + 1e-10f);
        sm[n] = fabsf(A[n]) < 1e-5f;
    }
    float h[Nd];
    const size_t ho = (((size_t)b * NCH + c) * Ed + e) * Nd;
#pragma unroll
    for (int n = 0; n < Nd; ++n) h[n] = g_hcarry[ho + n];
    const float dve = Dv[e];

    const size_t base = ((size_t)b * Ld + (size_t)c * CLs) * Ed + e;
    const size_t pidx = (c > 0) ? (base - Ed) : base;
    float pd = g_dt[pidx];
    float pu = g_u[pidx];
    for (int t = 0; t < CLs; ++t) {
#pragma unroll
        for (int n = 0; n < Nd; ++n) {
            const float em1 = expm1_small(pd * A[n]);
            const float a = 1.f + em1;
            const float bt = sm[n] ? pd : em1 * invA[n];
            h[n] = fmaf(a, h[n], bt * pu);
        }
        const float d_cur = g_dt[base + (size_t)t * Ed];
        const float u_cur = g_u[base + (size_t)t * Ed];
        const float z_cur = g_z[base + (size_t)t * Ed];
        float y = 0.f;
#pragma unroll
        for (int n = 0; n < Nd; ++n)
            y = fmaf(Cs[t][n], h[n], y);
        const float ys = fmaf(u_cur, dve, y);
        s_gh[base + (size_t)t * Ed] = __float2half_rn(ys * silu_f(z_cur));
        pd = d_cur;
        pu = u_cur;
    }
}

// ---------------- host launcher ----------------
extern "C" void kernel_launch(void* const* d_in, const int* in_sizes, int n_in,
                              void* d_out, int out_size)
{
    const float* x     = (const float*)d_in[0];
    const float* W_z   = (const float*)d_in[1];
    const float* W_p   = (const float*)d_in[2];
    const float* cw    = (const float*)d_in[3];
    const float* W_dt  = (const float*)d_in[4];
    const float* b_dt  = (const float*)d_in[5];
    const float* A_log = (const float*)d_in[6];
    const float* Dv    = (const float*)d_in[7];
    const float* W_o   = (const float*)d_in[8];
    float* out = (float*)d_out;

    float *z, *params, *dt;
    cudaGetSymbolAddress((void**)&z,      g_z);
    cudaGetSymbolAddress((void**)&params, g_params);
    cudaGetSymbolAddress((void**)&dt,     g_dt);

    __half *xh, *gh, *ph;
    __half *wzh, *wzl, *wph, *wpl, *wdh, *wdl, *woh, *wol;
    cudaGetSymbolAddress((void**)&xh, s_xh);
    cudaGetSymbolAddress((void**)&gh, s_gh);
    cudaGetSymbolAddress((void**)&ph, s_ph);
    cudaGetSymbolAddress((void**)&wzh, s_wzh); cudaGetSymbolAddress((void**)&wzl, s_wzl);
    cudaGetSymbolAddress((void**)&wph, s_wph); cudaGetSymbolAddress((void**)&wpl, s_wpl);
    cudaGetSymbolAddress((void**)&wdh, s_wdh); cudaGetSymbolAddress((void**)&wdl, s_wdl);
    cudaGetSymbolAddress((void**)&woh, s_woh); cudaGetSymbolAddress((void**)&wol, s_wol);

    cudaFuncSetAttribute(gemm_zp,  cudaFuncAttributeMaxDynamicSharedMemorySize, GSM);
    cudaFuncSetAttribute(gemm_gen, cudaFuncAttributeMaxDynamicSharedMemorySize, GSM);

    dim3 blk(256);

    // activation cast + weight splits
    cast_half_kernel<<<(Md * Ed / 4 + 255) / 256, blk>>>(x, xh, Md * Ed / 4);
    split_half_kernel<<<(Ed * Ed / 4 + 255) / 256, blk>>>(W_z,  wzh, wzl, Ed * Ed / 4);
    split_half_kernel<<<(Pd * Ed / 4 + 255) / 256, blk>>>(W_p,  wph, wpl, Pd * Ed / 4);
    split_half_kernel<<<(Ed * Rd / 4 + 255) / 256, blk>>>(W_dt, wdh, wdl, Ed * Rd / 4);
    split_half_kernel<<<(Ed * Ed / 4 + 255) / 256, blk>>>(W_o,  woh, wol, Ed * Ed / 4);

    // merged z + params GEMM (288 CTAs = one wave at 2 CTAs/SM)
    gemm_zp<<<dim3(9, Md / 128), blk, GSM>>>(xh, wzh, wzl, wph, wpl, z, params, ph);
    // dt = softplus(params[:, :64] @ W_dt^T + b_dt)   (K=64)
    gemm_gen<<<dim3(Ed / 128, Md / 128), blk, GSM>>>(ph, Pd, wdh, wdl, Rd,
                                                     dt, Ed, Rd, b_dt);
    // u = silu(causal depthwise conv(x))
    conv_silu_kernel<<<(Md / 4) * (Ed / 4) / 256, blk>>>(x, cw);
    // chunked scan (reference's one-step-delayed recurrence)
    scan_phaseA<<<dim3(Ed / 256, NCH, Bd), blk>>>(A_log);
    scan_phaseB<<<(Bd * Ed * Nd) / 256, blk>>>();
    scan_phaseC<<<dim3(Ed / 256, NCH, Bd), blk>>>(A_log, Dv);
    // out = g @ W_out^T
    gemm_gen<<<dim3(Ed / 128, Md / 128), blk, GSM>>>(gh, Ed, woh, wol, Ed,
                                                     out, Ed, Ed, nullptr);
}

// round 7
// speedup vs baseline: 3.0251x; 1.1118x over previous
#include <cuda_runtime.h>
#include <cuda_fp16.h>
#include <math.h>
#include <stdint.h>

// Problem constants
#define Ed 1024
#define Nd 16
#define Kd 4
#define Rd 64
#define Bd 2
#define Ld 2048
#define Pd 96          // R + 2N
#define CLs 64         // chunk length for scan
#define NCH 32         // L / CLs
#define Md (Bd * Ld)   // 4096 tokens

// ---------------- scratch (static device memory; no allocation) ----------------
__device__ __align__(128) float g_z[(size_t)Md * Ed];
__device__ __align__(128) float g_params[(size_t)Md * Pd];
__device__ __align__(128) float g_u[(size_t)Md * Ed];
__device__ __align__(128) __half g_dt16[(size_t)Md * Ed];
__device__ __align__(128) float g_hend[(size_t)Bd * NCH * Ed * Nd];
__device__ __align__(128) float g_P[(size_t)Bd * NCH * Ed * Nd];
__device__ __align__(128) float g_hcarry[(size_t)Bd * NCH * Ed * Nd];

// fp16 planes
__device__ __align__(128) __half s_xh[(size_t)Md * Ed];
__device__ __align__(128) __half s_gh[(size_t)Md * Ed];
__device__ __align__(128) __half s_ph[(size_t)Md * Pd];
__device__ __align__(128) __half s_wzh[(size_t)Ed * Ed];
__device__ __align__(128) __half s_wph[(size_t)Pd * Ed];
__device__ __align__(128) __half s_wdh[(size_t)Ed * Rd];
__device__ __align__(128) __half s_woh[(size_t)Ed * Ed];

__device__ __forceinline__ float softplus_f(float v) {
    return v > 20.f ? v : log1pf(expf(v));
}
__device__ __forceinline__ float silu_f(float v) {
    return v / (1.f + expf(-v));
}
// expm1 for small negative y (dt*A in [-0.03, 0] in practice); guarded fallback.
__device__ __forceinline__ float expm1_small(float y) {
    if (y > -0.0625f) {
        return y * (1.f + y * (0.5f + y * (0.16666667f + y * 0.041666667f)));
    }
    return expf(y) - 1.f;
}

// ---------------- fp32 -> fp16 cast ----------------
__global__ __launch_bounds__(256)
void cast_half_kernel(const float* __restrict__ in, __half* __restrict__ out, int n4)
{
    int i = blockIdx.x * 256 + threadIdx.x;
    if (i >= n4) return;
    const float4 v = reinterpret_cast<const float4*>(in)[i];
    reinterpret_cast<__half2*>(out)[i * 2 + 0] = __floats2half2_rn(v.x, v.y);
    reinterpret_cast<__half2*>(out)[i * 2 + 1] = __floats2half2_rn(v.z, v.w);
}

// ================= fp16 GEMM: Y[M,n] = A[M,K] @ W[N,K]^T =================
// Block 128x128, K-chunk 64 double-buffered, 8 warps (2x4), warp tile 64x32.

#define TSTR2 72                       // smem row stride in fp16 (144 B)
#define PLN (128 * TSTR2 * 2)          // 18432 B per plane
#define STG (2 * PLN)                  // A, Bh = 36864 B
#define GSM (2 * STG)                  // 73728 B

__device__ __forceinline__ void cp16(uint32_t sdst, const void* gsrc, int nbytes) {
    asm volatile("cp.async.cg.shared.global [%0], [%1], 16, %2;"
                 :: "r"(sdst), "l"(gsrc), "r"(nbytes));
}
__device__ __forceinline__ void ldm_x4(uint32_t a, uint32_t& r0, uint32_t& r1,
                                       uint32_t& r2, uint32_t& r3) {
    asm volatile("ldmatrix.sync.aligned.m8n8.x4.shared.b16 {%0,%1,%2,%3}, [%4];"
                 : "=r"(r0), "=r"(r1), "=r"(r2), "=r"(r3) : "r"(a));
}
__device__ __forceinline__ void ldm_x2(uint32_t a, uint32_t& r0, uint32_t& r1) {
    asm volatile("ldmatrix.sync.aligned.m8n8.x2.shared.b16 {%0,%1}, [%2];"
                 : "=r"(r0), "=r"(r1) : "r"(a));
}
__device__ __forceinline__ void mma_f16(float* d, const uint32_t* a, const uint32_t* b) {
    asm volatile(
        "mma.sync.aligned.m16n8k16.row.col.f32.f16.f16.f32 "
        "{%0,%1,%2,%3}, {%4,%5,%6,%7}, {%8,%9}, {%0,%1,%2,%3};"
        : "+f"(d[0]), "+f"(d[1]), "+f"(d[2]), "+f"(d[3])
        : "r"(a[0]), "r"(a[1]), "r"(a[2]), "r"(a[3]), "r"(b[0]), "r"(b[1]));
}

// load one 128x64 fp16 tile (row zfill guard) into an smem plane
__device__ __forceinline__ void ldp64(uint32_t sdst, const __half* src, int ld,
                                      int row0, int k0, int rows_valid)
{
    const int tid = threadIdx.x;
#pragma unroll
    for (int it = 0; it < 4; ++it) {
        const int slot = tid + (it << 8);     // 0..1023
        const int row = slot >> 3;            // 0..127
        const int kg = slot & 7;              // 0..7 (8 halves each)
        const int rv = (row < rows_valid);
        cp16(sdst + (uint32_t)(row * TSTR2 + kg * 8) * 2,
             src + (size_t)(row0 + (rv ? row : 0)) * ld + k0 + kg * 8,
             rv ? 16 : 0);
    }
}

__device__ __forceinline__ void gemm_core(
    uint32_t sb, const __half* __restrict__ Ah, int lda,
    const __half* __restrict__ Bh, int ldb, int nvB, int Ktot,
    int bm, int bn, float acc[4][4][4])
{
    const int tid = threadIdx.x, wid = tid >> 5, lane = tid & 31;
    const int wm = wid & 1, wn = wid >> 1;
    const int NKT = Ktot >> 6;

    ldp64(sb + 0 * PLN, Ah, lda, bm, 0, 128);
    ldp64(sb + 1 * PLN, Bh, ldb, bn, 0, nvB);
    asm volatile("cp.async.commit_group;" ::: "memory");
    asm volatile("cp.async.wait_group 0;" ::: "memory");
    __syncthreads();

    const int lr = lane & 7;
    const int ag1 = (lane >> 3) & 1;
    const int ag2 = (lane >> 4) & 1;
    const int bg1 = (lane >> 3) & 1;

    for (int kt = 0; kt < NKT; ++kt) {
        const uint32_t st = sb + (uint32_t)(kt & 1) * STG;
        if (kt + 1 < NKT) {
            const uint32_t st2 = sb + (uint32_t)((kt + 1) & 1) * STG;
            const int k0 = (kt + 1) << 6;
            ldp64(st2 + 0 * PLN, Ah, lda, bm, k0, 128);
            ldp64(st2 + 1 * PLN, Bh, ldb, bn, k0, nvB);
            asm volatile("cp.async.commit_group;" ::: "memory");
        }
#pragma unroll
        for (int ks = 0; ks < 4; ++ks) {
            uint32_t ah[4][4], bh[4][2];
#pragma unroll
            for (int mi = 0; mi < 4; ++mi) {
                const uint32_t off = (uint32_t)((wm * 64 + mi * 16 + ag1 * 8 + lr) * TSTR2
                                                + ks * 16 + ag2 * 8) * 2;
                ldm_x4(st + 0 * PLN + off, ah[mi][0], ah[mi][1], ah[mi][2], ah[mi][3]);
            }
#pragma unroll
            for (int ni = 0; ni < 4; ++ni) {
                const uint32_t off = (uint32_t)((wn * 32 + ni * 8 + lr) * TSTR2
                                                + ks * 16 + bg1 * 8) * 2;
                ldm_x2(st + 1 * PLN + off, bh[ni][0], bh[ni][1]);
            }
#pragma unroll
            for (int mi = 0; mi < 4; ++mi)
#pragma unroll
                for (int ni = 0; ni < 4; ++ni)
                    mma_f16(acc[mi][ni], ah[mi], bh[ni]);
        }
        asm volatile("cp.async.wait_group 0;" ::: "memory");
        __syncthreads();
    }
}

// merged z + params GEMM: bx<8 -> z tile; bx==8 -> params tile (also emits ph fp16)
__global__ __launch_bounds__(256, 2)
void gemm_zp(const __half* __restrict__ xh,
             const __half* __restrict__ wzh, const __half* __restrict__ wph,
             float* __restrict__ z, float* __restrict__ params,
             __half* __restrict__ ph)
{
    extern __shared__ char smem[];
    const uint32_t sb = (uint32_t)__cvta_generic_to_shared(smem);
    const int tid = threadIdx.x, wid = tid >> 5, lane = tid & 31;
    const int wm = wid & 1, wn = wid >> 1;
    const int bx = blockIdx.x, bm = blockIdx.y * 128;

    float acc[4][4][4];
#pragma unroll
    for (int i = 0; i < 4; ++i)
#pragma unroll
        for (int j = 0; j < 4; ++j)
#pragma unroll
            for (int k = 0; k < 4; ++k) acc[i][j][k] = 0.f;

    if (bx < 8) {
        gemm_core(sb, xh, Ed, wzh, Ed, 128, Ed, bm, bx * 128, acc);
#pragma unroll
        for (int mi = 0; mi < 4; ++mi) {
            const int row = bm + wm * 64 + mi * 16 + (lane >> 2);
#pragma unroll
            for (int ni = 0; ni < 4; ++ni) {
                const int col = bx * 128 + wn * 32 + ni * 8 + (lane & 3) * 2;
                *reinterpret_cast<float2*>(&z[(size_t)row * Ed + col]) =
                    make_float2(acc[mi][ni][0], acc[mi][ni][1]);
                *reinterpret_cast<float2*>(&z[(size_t)(row + 8) * Ed + col]) =
                    make_float2(acc[mi][ni][2], acc[mi][ni][3]);
            }
        }
    } else {
        gemm_core(sb, xh, Ed, wph, Ed, Pd, Ed, bm, 0, acc);
#pragma unroll
        for (int mi = 0; mi < 4; ++mi) {
            const int r0 = bm + wm * 64 + mi * 16 + (lane >> 2);
#pragma unroll
            for (int ni = 0; ni < 4; ++ni) {
                const int col = wn * 32 + ni * 8 + (lane & 3) * 2;
                if (col >= Pd) continue;
#pragma unroll
                for (int hh = 0; hh < 2; ++hh) {
                    const int row = r0 + hh * 8;
                    const float v0 = acc[mi][ni][hh * 2 + 0];
                    const float v1 = acc[mi][ni][hh * 2 + 1];
                    *reinterpret_cast<float2*>(&params[(size_t)row * Pd + col]) =
                        make_float2(v0, v1);
                    if (col < Rd) {
                        __half2 hv; hv.x = __float2half_rn(v0); hv.y = __float2half_rn(v1);
                        *reinterpret_cast<__half2*>(&ph[(size_t)row * Pd + col]) = hv;
                    }
                }
            }
        }
    }
}

// generic GEMM. EPI 0: fp32 out. EPI 1: softplus(acc + bias) -> fp16 out.
template <int EPI>
__global__ __launch_bounds__(256, 2)
void gemm_gen(const __half* __restrict__ Ah, int lda,
              const __half* __restrict__ Bh, int ldb,
              void* __restrict__ Yv, int ldy, int Ktot,
              const float* __restrict__ bias)
{
    extern __shared__ char smem[];
    const uint32_t sb = (uint32_t)__cvta_generic_to_shared(smem);
    const int tid = threadIdx.x, wid = tid >> 5, lane = tid & 31;
    const int wm = wid & 1, wn = wid >> 1;
    const int bm = blockIdx.y * 128, bn = blockIdx.x * 128;

    float acc[4][4][4];
#pragma unroll
    for (int i = 0; i < 4; ++i)
#pragma unroll
        for (int j = 0; j < 4; ++j)
#pragma unroll
            for (int k = 0; k < 4; ++k) acc[i][j][k] = 0.f;

    gemm_core(sb, Ah, lda, Bh, ldb, 128, Ktot, bm, bn, acc);

#pragma unroll
    for (int mi = 0; mi < 4; ++mi) {
        const int row = bm + wm * 64 + mi * 16 + (lane >> 2);
#pragma unroll
        for (int ni = 0; ni < 4; ++ni) {
            const int col = bn + wn * 32 + ni * 8 + (lane & 3) * 2;
            if (EPI == 0) {
                float* Y = (float*)Yv;
                *reinterpret_cast<float2*>(&Y[(size_t)row * ldy + col]) =
                    make_float2(acc[mi][ni][0], acc[mi][ni][1]);
                *reinterpret_cast<float2*>(&Y[(size_t)(row + 8) * ldy + col]) =
                    make_float2(acc[mi][ni][2], acc[mi][ni][3]);
            } else {
                __half* Y = (__half*)Yv;
                const float b0 = bias[col], b1 = bias[col + 1];
                __half2 h01, h23;
                h01.x = __float2half_rn(softplus_f(acc[mi][ni][0] + b0));
                h01.y = __float2half_rn(softplus_f(acc[mi][ni][1] + b1));
                h23.x = __float2half_rn(softplus_f(acc[mi][ni][2] + b0));
                h23.y = __float2half_rn(softplus_f(acc[mi][ni][3] + b1));
                *reinterpret_cast<__half2*>(&Y[(size_t)row * ldy + col]) = h01;
                *reinterpret_cast<__half2*>(&Y[(size_t)(row + 8) * ldy + col]) = h23;
            }
        }
    }
}

// ---------------- scan phase A: fused depthwise-conv + per-chunk local scan --------
// Reference recurrence: h[0]=bt[0]*u[0]; h[t]=a[t-1]*h[t-1]+bt[t-1]*u[t-1].
// u computed on-the-fly from x via rolling 4-tap window; u written out for phase C.
__global__ __launch_bounds__(256)
void scan_phaseA(const float* __restrict__ A_log,
                 const float* __restrict__ x, const float* __restrict__ cw)
{
    const int e = blockIdx.x * 256 + threadIdx.x;
    const int c = blockIdx.y, b = blockIdx.z;
    float A[Nd], invA[Nd];
    bool sm[Nd];
#pragma unroll
    for (int n = 0; n < Nd; ++n) {
        A[n] = -expf(A_log[(size_t)e * Nd + n]);
        invA[n] = 1.f / (A[n] + 1e-10f);
        sm[n] = fabsf(A[n]) < 1e-5f;
    }
    float h[Nd], P[Nd];
#pragma unroll
    for (int n = 0; n < Nd; ++n) { h[n] = 0.f; P[n] = 1.f; }

    const size_t rowbase = (size_t)b * Ld * Ed + e;
    const int l0 = c * CLs;
    const int lprev = (c > 0) ? (l0 - 1) : l0;

    const float4 wcv = *reinterpret_cast<const float4*>(&cw[(size_t)e * Kd]);
    float x0, x1, x2, x3;
    {
        int l = lprev - 3;
        x0 = (l >= 0) ? x[rowbase + (size_t)l * Ed] : 0.f; ++l;
        x1 = (l >= 0) ? x[rowbase + (size_t)l * Ed] : 0.f; ++l;
        x2 = (l >= 0) ? x[rowbase + (size_t)l * Ed] : 0.f; ++l;
        x3 = x[rowbase + (size_t)l * Ed];
    }
    float pu = silu_f(wcv.x * x0 + wcv.y * x1 + wcv.z * x2 + wcv.w * x3);
    float pd = __half2float(g_dt16[rowbase + (size_t)lprev * Ed]);

    for (int t = 0; t < CLs; ++t) {
#pragma unroll
        for (int n = 0; n < Nd; ++n) {
            const float em1 = expm1_small(pd * A[n]);
            const float a = 1.f + em1;
            const float bt = sm[n] ? pd : em1 * invA[n];
            h[n] = fmaf(a, h[n], bt * pu);
            P[n] *= a;
        }
        const int lcur = l0 + t;
        float ucur;
        if (c == 0 && t == 0) {
            ucur = pu;                      // index 0 reused
        } else {
            x0 = x1; x1 = x2; x2 = x3;
            x3 = x[rowbase + (size_t)lcur * Ed];
            ucur = silu_f(wcv.x * x0 + wcv.y * x1 + wcv.z * x2 + wcv.w * x3);
        }
        g_u[rowbase + (size_t)lcur * Ed] = ucur;
        pd = __half2float(g_dt16[rowbase + (size_t)lcur * Ed]);
        pu = ucur;
    }
    const size_t ho = (((size_t)b * NCH + c) * Ed + e) * Nd;
#pragma unroll
    for (int n = 0; n < Nd; ++n) { g_hend[ho + n] = h[n]; g_P[ho + n] = P[n]; }
}

// ---------------- scan phase B: combine chunk carries (per b,e,n thread) ----------
__global__ __launch_bounds__(256)
void scan_phaseB()
{
    const int gid = blockIdx.x * 256 + threadIdx.x;   // 0 .. B*E*N-1
    const int n = gid & (Nd - 1);
    const int e = (gid >> 4) & (Ed - 1);
    const int b = gid >> 14;
    float h = 0.f;
    size_t idx = (((size_t)b * NCH) * Ed + e) * Nd + n;
    const size_t stride = (size_t)Ed * Nd;
    for (int c = 0; c < NCH; ++c) {
        g_hcarry[idx] = h;
        h = fmaf(g_P[idx], h, g_hend[idx]);
        idx += stride;
    }
}

// ---------------- scan phase C: rescan with carry, compute y, gate -> gh (fp16) ----
__global__ __launch_bounds__(256)
void scan_phaseC(const float* __restrict__ A_log, const float* __restrict__ Dv)
{
    __shared__ float Cs[CLs][Nd];   // 4 KB, broadcast reads
    const int e = blockIdx.x * 256 + threadIdx.x;
    const int c = blockIdx.y, b = blockIdx.z;
    const size_t pbase = ((size_t)b * Ld + (size_t)c * CLs) * Pd;
    for (int i = threadIdx.x; i < CLs * Nd; i += 256) {
        const int t = i >> 4, n = i & 15;
        Cs[t][n] = g_params[pbase + (size_t)t * Pd + (Rd + Nd) + n];
    }
    __syncthreads();

    float A[Nd], invA[Nd];
    bool sm[Nd];
#pragma unroll
    for (int n = 0; n < Nd; ++n) {
        A[n] = -expf(A_log[(size_t)e * Nd + n]);
        invA[n] = 1.f / (A[n] + 1e-10f);
        sm[n] = fabsf(A[n]) < 1e-5f;
    }
    float h[Nd];
    const size_t ho = (((size_t)b * NCH + c) * Ed + e) * Nd;
#pragma unroll
    for (int n = 0; n < Nd; ++n) h[n] = g_hcarry[ho + n];
    const float dve = Dv[e];

    const size_t base = ((size_t)b * Ld + (size_t)c * CLs) * Ed + e;
    const size_t pidx = (c > 0) ? (base - Ed) : base;
    float pd = __half2float(g_dt16[pidx]);
    float pu = g_u[pidx];
    for (int t = 0; t < CLs; ++t) {
#pragma unroll
        for (int n = 0; n < Nd; ++n) {
            const float em1 = expm1_small(pd * A[n]);
            const float a = 1.f + em1;
            const float bt = sm[n] ? pd : em1 * invA[n];
            h[n] = fmaf(a, h[n], bt * pu);
        }
        const float d_cur = __half2float(g_dt16[base + (size_t)t * Ed]);
        const float u_cur = g_u[base + (size_t)t * Ed];
        const float z_cur = g_z[base + (size_t)t * Ed];
        float y = 0.f;
#pragma unroll
        for (int n = 0; n < Nd; ++n)
            y = fmaf(Cs[t][n], h[n], y);
        const float ys = fmaf(u_cur, dve, y);
        s_gh[base + (size_t)t * Ed] = __float2half_rn(ys * silu_f(z_cur));
        pd = d_cur;
        pu = u_cur;
    }
}

// ---------------- host launcher ----------------
extern "C" void kernel_launch(void* const* d_in, const int* in_sizes, int n_in,
                              void* d_out, int out_size)
{
    const float* x     = (const float*)d_in[0];
    const float* W_z   = (const float*)d_in[1];
    const float* W_p   = (const float*)d_in[2];
    const float* cw    = (const float*)d_in[3];
    const float* W_dt  = (const float*)d_in[4];
    const float* b_dt  = (const float*)d_in[5];
    const float* A_log = (const float*)d_in[6];
    const float* Dv    = (const float*)d_in[7];
    const float* W_o   = (const float*)d_in[8];
    float* out = (float*)d_out;

    float *z, *params;
    __half *dt16;
    cudaGetSymbolAddress((void**)&z,      g_z);
    cudaGetSymbolAddress((void**)&params, g_params);
    cudaGetSymbolAddress((void**)&dt16,   g_dt16);

    __half *xh, *gh, *ph, *wzh, *wph, *wdh, *woh;
    cudaGetSymbolAddress((void**)&xh, s_xh);
    cudaGetSymbolAddress((void**)&gh, s_gh);
    cudaGetSymbolAddress((void**)&ph, s_ph);
    cudaGetSymbolAddress((void**)&wzh, s_wzh);
    cudaGetSymbolAddress((void**)&wph, s_wph);
    cudaGetSymbolAddress((void**)&wdh, s_wdh);
    cudaGetSymbolAddress((void**)&woh, s_woh);

    cudaFuncSetAttribute(gemm_zp,     cudaFuncAttributeMaxDynamicSharedMemorySize, GSM);
    cudaFuncSetAttribute(gemm_gen<0>, cudaFuncAttributeMaxDynamicSharedMemorySize, GSM);
    cudaFuncSetAttribute(gemm_gen<1>, cudaFuncAttributeMaxDynamicSharedMemorySize, GSM);

    dim3 blk(256);

    // casts to fp16
    cast_half_kernel<<<(Md * Ed / 4 + 255) / 256, blk>>>(x,    xh,  Md * Ed / 4);
    cast_half_kernel<<<(Ed * Ed / 4 + 255) / 256, blk>>>(W_z,  wzh, Ed * Ed / 4);
    cast_half_kernel<<<(Pd * Ed / 4 + 255) / 256, blk>>>(W_p,  wph, Pd * Ed / 4);
    cast_half_kernel<<<(Ed * Rd / 4 + 255) / 256, blk>>>(W_dt, wdh, Ed * Rd / 4);
    cast_half_kernel<<<(Ed * Ed / 4 + 255) / 256, blk>>>(W_o,  woh, Ed * Ed / 4);

    // merged z + params GEMM
    gemm_zp<<<dim3(9, Md / 128), blk, GSM>>>(xh, wzh, wph, z, params, ph);
    // dt16 = softplus(params[:, :64] @ W_dt^T + b_dt)   (K=64, fp16 out)
    gemm_gen<1><<<dim3(Ed / 128, Md / 128), blk, GSM>>>(ph, Pd, wdh, Rd,
                                                        dt16, Ed, Rd, b_dt);
    // chunked scan (conv+SiLU fused into phase A)
    scan_phaseA<<<dim3(Ed / 256, NCH, Bd), blk>>>(A_log, x, cw);
    scan_phaseB<<<(Bd * Ed * Nd) / 256, blk>>>();
    scan_phaseC<<<dim3(Ed / 256, NCH, Bd), blk>>>(A_log, Dv);
    // out = g @ W_out^T
    gemm_gen<0><<<dim3(Ed / 128, Md / 128), blk, GSM>>>(gh, Ed, woh, Ed,
                                                        out, Ed, Ed, nullptr);
}

// round 8
// speedup vs baseline: 3.3064x; 1.0930x over previous
#include <cuda_runtime.h>
#include <cuda_fp16.h>
#include <math.h>
#include <stdint.h>

// Problem constants
#define Ed 1024
#define Nd 16
#define Kd 4
#define Rd 64
#define Bd 2
#define Ld 2048
#define Pd 96          // R + 2N
#define CLs 64         // chunk length for scan
#define NCH 32         // L / CLs
#define Md (Bd * Ld)   // 4096 tokens

// ---------------- scratch (static device memory; no allocation) ----------------
__device__ __align__(128) float g_C[(size_t)Md * Nd];        // compact C_proj
__device__ __align__(128) __half g_dt16[(size_t)Md * Ed];
__device__ __align__(128) float g_hend[(size_t)Bd * NCH * Ed * Nd];
__device__ __align__(128) float g_P[(size_t)Bd * NCH * Ed * Nd];
__device__ __align__(128) float g_hcarry[(size_t)Bd * NCH * Ed * Nd];

// fp16 planes
__device__ __align__(128) __half s_xh[(size_t)Md * Ed];
__device__ __align__(128) __half s_zh[(size_t)Md * Ed];
__device__ __align__(128) __half s_uh[(size_t)Md * Ed];
__device__ __align__(128) __half s_gh[(size_t)Md * Ed];
__device__ __align__(128) __half s_ph[(size_t)Md * Pd];
__device__ __align__(128) __half s_wzh[(size_t)Ed * Ed];
__device__ __align__(128) __half s_wph[(size_t)Pd * Ed];
__device__ __align__(128) __half s_wdh[(size_t)Ed * Rd];
__device__ __align__(128) __half s_woh[(size_t)Ed * Ed];

__device__ __forceinline__ float softplus_f(float v) {
    return v > 20.f ? v : log1pf(expf(v));
}
__device__ __forceinline__ float silu_f(float v) {
    return v / (1.f + expf(-v));
}
// expm1 for small negative y (dt*A in [-0.03, 0] in practice); guarded fallback.
__device__ __forceinline__ float expm1_small(float y) {
    if (y > -0.0625f) {
        return y * (1.f + y * (0.5f + y * (0.16666667f + y * 0.041666667f)));
    }
    return expf(y) - 1.f;
}

// ---------------- single merged fp32 -> fp16 cast over all 5 tensors ----------------
#define CN0 (Md * Ed / 4)
#define CN1 (Ed * Ed / 4)
#define CN2 (Pd * Ed / 4)
#define CN3 (Ed * Rd / 4)
#define CN4 (Ed * Ed / 4)
#define CNT (CN0 + CN1 + CN2 + CN3 + CN4)

__global__ __launch_bounds__(256)
void cast_all_kernel(const float* __restrict__ x,  const float* __restrict__ wz,
                     const float* __restrict__ wp, const float* __restrict__ wdt,
                     const float* __restrict__ wo)
{
    int j = blockIdx.x * 256 + threadIdx.x;
    const float* in; __half* out;
    if (j < CN0)              { in = x;   out = s_xh;  }
    else if ((j -= CN0) < CN1){ in = wz;  out = s_wzh; }
    else if ((j -= CN1) < CN2){ in = wp;  out = s_wph; }
    else if ((j -= CN2) < CN3){ in = wdt; out = s_wdh; }
    else if ((j -= CN3) < CN4){ in = wo;  out = s_woh; }
    else return;
    const float4 v = reinterpret_cast<const float4*>(in)[j];
    reinterpret_cast<__half2*>(out)[j * 2 + 0] = __floats2half2_rn(v.x, v.y);
    reinterpret_cast<__half2*>(out)[j * 2 + 1] = __floats2half2_rn(v.z, v.w);
}

// ================= fp16 GEMM: Y[M,n] = A[M,K] @ W[N,K]^T =================
// Block 128x128, K-chunk 64, 3-stage cp.async pipeline, 8 warps, warp tile 64x32.

#define TSTR2 72                       // smem row stride in fp16 (144 B)
#define PLN (128 * TSTR2 * 2)          // 18432 B per plane
#define STG (2 * PLN)                  // A, B = 36864 B
#define GSM (3 * STG)                  // 110592 B (3 stages)

__device__ __forceinline__ void cp16(uint32_t sdst, const void* gsrc, int nbytes) {
    asm volatile("cp.async.cg.shared.global [%0], [%1], 16, %2;"
                 :: "r"(sdst), "l"(gsrc), "r"(nbytes));
}
__device__ __forceinline__ void ldm_x4(uint32_t a, uint32_t& r0, uint32_t& r1,
                                       uint32_t& r2, uint32_t& r3) {
    asm volatile("ldmatrix.sync.aligned.m8n8.x4.shared.b16 {%0,%1,%2,%3}, [%4];"
                 : "=r"(r0), "=r"(r1), "=r"(r2), "=r"(r3) : "r"(a));
}
__device__ __forceinline__ void ldm_x2(uint32_t a, uint32_t& r0, uint32_t& r1) {
    asm volatile("ldmatrix.sync.aligned.m8n8.x2.shared.b16 {%0,%1}, [%2];"
                 : "=r"(r0), "=r"(r1) : "r"(a));
}
__device__ __forceinline__ void mma_f16(float* d, const uint32_t* a, const uint32_t* b) {
    asm volatile(
        "mma.sync.aligned.m16n8k16.row.col.f32.f16.f16.f32 "
        "{%0,%1,%2,%3}, {%4,%5,%6,%7}, {%8,%9}, {%0,%1,%2,%3};"
        : "+f"(d[0]), "+f"(d[1]), "+f"(d[2]), "+f"(d[3])
        : "r"(a[0]), "r"(a[1]), "r"(a[2]), "r"(a[3]), "r"(b[0]), "r"(b[1]));
}

// load one 128x64 fp16 tile (row zfill guard) into an smem plane
__device__ __forceinline__ void ldp64(uint32_t sdst, const __half* src, int ld,
                                      int row0, int k0, int rows_valid)
{
    const int tid = threadIdx.x;
#pragma unroll
    for (int it = 0; it < 4; ++it) {
        const int slot = tid + (it << 8);     // 0..1023
        const int row = slot >> 3;            // 0..127
        const int kg = slot & 7;              // 0..7 (8 halves each)
        const int rv = (row < rows_valid);
        cp16(sdst + (uint32_t)(row * TSTR2 + kg * 8) * 2,
             src + (size_t)(row0 + (rv ? row : 0)) * ld + k0 + kg * 8,
             rv ? 16 : 0);
    }
}

__device__ __forceinline__ void gemm_core(
    uint32_t sb, const __half* __restrict__ Ah, int lda,
    const __half* __restrict__ Bh, int ldb, int nvB, int Ktot,
    int bm, int bn, float acc[4][4][4])
{
    const int tid = threadIdx.x, wid = tid >> 5, lane = tid & 31;
    const int wm = wid & 1, wn = wid >> 1;
    const int NKT = Ktot >> 6;

    // prologue: stages 0 and 1 (group committed even if empty)
    ldp64(sb + 0 * STG + 0 * PLN, Ah, lda, bm, 0, 128);
    ldp64(sb + 0 * STG + 1 * PLN, Bh, ldb, bn, 0, nvB);
    asm volatile("cp.async.commit_group;" ::: "memory");
    if (NKT > 1) {
        ldp64(sb + 1 * STG + 0 * PLN, Ah, lda, bm, 64, 128);
        ldp64(sb + 1 * STG + 1 * PLN, Bh, ldb, bn, 64, nvB);
    }
    asm volatile("cp.async.commit_group;" ::: "memory");

    const int lr = lane & 7;
    const int ag1 = (lane >> 3) & 1;
    const int ag2 = (lane >> 4) & 1;
    const int bg1 = (lane >> 3) & 1;

    int cur = 0, pf = 2;
    for (int kt = 0; kt < NKT; ++kt) {
        // stage kt is group kt+1 of kt+2 committed; wait_group 1 -> ready
        asm volatile("cp.async.wait_group 1;" ::: "memory");
        __syncthreads();
        if (kt + 2 < NKT) {
            const uint32_t st2 = sb + (uint32_t)pf * STG;
            const int k0 = (kt + 2) << 6;
            ldp64(st2 + 0 * PLN, Ah, lda, bm, k0, 128);
            ldp64(st2 + 1 * PLN, Bh, ldb, bn, k0, nvB);
        }
        asm volatile("cp.async.commit_group;" ::: "memory");

        const uint32_t st = sb + (uint32_t)cur * STG;
#pragma unroll
        for (int ks = 0; ks < 4; ++ks) {
            uint32_t ah[4][4], bh[4][2];
#pragma unroll
            for (int mi = 0; mi < 4; ++mi) {
                const uint32_t off = (uint32_t)((wm * 64 + mi * 16 + ag1 * 8 + lr) * TSTR2
                                                + ks * 16 + ag2 * 8) * 2;
                ldm_x4(st + 0 * PLN + off, ah[mi][0], ah[mi][1], ah[mi][2], ah[mi][3]);
            }
#pragma unroll
            for (int ni = 0; ni < 4; ++ni) {
                const uint32_t off = (uint32_t)((wn * 32 + ni * 8 + lr) * TSTR2
                                                + ks * 16 + bg1 * 8) * 2;
                ldm_x2(st + 1 * PLN + off, bh[ni][0], bh[ni][1]);
            }
#pragma unroll
            for (int mi = 0; mi < 4; ++mi)
#pragma unroll
                for (int ni = 0; ni < 4; ++ni)
                    mma_f16(acc[mi][ni], ah[mi], bh[ni]);
        }
        cur = (cur == 2) ? 0 : cur + 1;
        pf  = (pf  == 2) ? 0 : pf  + 1;
    }
    asm volatile("cp.async.wait_group 0;" ::: "memory");
}

// merged z + params GEMM: bx<8 -> z tile (fp16 out); bx==8 -> params (ph + compact C)
__global__ __launch_bounds__(256, 2)
void gemm_zp(const __half* __restrict__ xh,
             const __half* __restrict__ wzh, const __half* __restrict__ wph,
             __half* __restrict__ zh, float* __restrict__ Cc,
             __half* __restrict__ ph)
{
    extern __shared__ char smem[];
    const uint32_t sb = (uint32_t)__cvta_generic_to_shared(smem);
    const int tid = threadIdx.x, wid = tid >> 5, lane = tid & 31;
    const int wm = wid & 1, wn = wid >> 1;
    const int bx = blockIdx.x, bm = blockIdx.y * 128;

    float acc[4][4][4];
#pragma unroll
    for (int i = 0; i < 4; ++i)
#pragma unroll
        for (int j = 0; j < 4; ++j)
#pragma unroll
            for (int k = 0; k < 4; ++k) acc[i][j][k] = 0.f;

    if (bx < 8) {
        gemm_core(sb, xh, Ed, wzh, Ed, 128, Ed, bm, bx * 128, acc);
#pragma unroll
        for (int mi = 0; mi < 4; ++mi) {
            const int row = bm + wm * 64 + mi * 16 + (lane >> 2);
#pragma unroll
            for (int ni = 0; ni < 4; ++ni) {
                const int col = bx * 128 + wn * 32 + ni * 8 + (lane & 3) * 2;
                __half2 h01, h23;
                h01.x = __float2half_rn(acc[mi][ni][0]);
                h01.y = __float2half_rn(acc[mi][ni][1]);
                h23.x = __float2half_rn(acc[mi][ni][2]);
                h23.y = __float2half_rn(acc[mi][ni][3]);
                *reinterpret_cast<__half2*>(&zh[(size_t)row * Ed + col]) = h01;
                *reinterpret_cast<__half2*>(&zh[(size_t)(row + 8) * Ed + col]) = h23;
            }
        }
    } else {
        gemm_core(sb, xh, Ed, wph, Ed, Pd, Ed, bm, 0, acc);
#pragma unroll
        for (int mi = 0; mi < 4; ++mi) {
            const int r0 = bm + wm * 64 + mi * 16 + (lane >> 2);
#pragma unroll
            for (int ni = 0; ni < 4; ++ni) {
                const int col = wn * 32 + ni * 8 + (lane & 3) * 2;
#pragma unroll
                for (int hh = 0; hh < 2; ++hh) {
                    const int row = r0 + hh * 8;
                    const float v0 = acc[mi][ni][hh * 2 + 0];
                    const float v1 = acc[mi][ni][hh * 2 + 1];
                    if (col < Rd) {                 // dt_unproj -> ph (fp16)
                        __half2 hv; hv.x = __float2half_rn(v0); hv.y = __float2half_rn(v1);
                        *reinterpret_cast<__half2*>(&ph[(size_t)row * Pd + col]) = hv;
                    } else if (col >= Rd + Nd && col < Pd) {   // C_proj -> compact
                        *reinterpret_cast<float2*>(&Cc[(size_t)row * Nd + (col - Rd - Nd)]) =
                            make_float2(v0, v1);
                    }
                }
            }
        }
    }
}

// generic GEMM. EPI 0: fp32 out. EPI 1: softplus(acc + bias) -> fp16 out.
template <int EPI>
__global__ __launch_bounds__(256, 2)
void gemm_gen(const __half* __restrict__ Ah, int lda,
              const __half* __restrict__ Bh, int ldb,
              void* __restrict__ Yv, int ldy, int Ktot,
              const float* __restrict__ bias)
{
    extern __shared__ char smem[];
    const uint32_t sb = (uint32_t)__cvta_generic_to_shared(smem);
    const int tid = threadIdx.x, wid = tid >> 5, lane = tid & 31;
    const int wm = wid & 1, wn = wid >> 1;
    const int bm = blockIdx.y * 128, bn = blockIdx.x * 128;

    float acc[4][4][4];
#pragma unroll
    for (int i = 0; i < 4; ++i)
#pragma unroll
        for (int j = 0; j < 4; ++j)
#pragma unroll
            for (int k = 0; k < 4; ++k) acc[i][j][k] = 0.f;

    gemm_core(sb, Ah, lda, Bh, ldb, 128, Ktot, bm, bn, acc);

#pragma unroll
    for (int mi = 0; mi < 4; ++mi) {
        const int row = bm + wm * 64 + mi * 16 + (lane >> 2);
#pragma unroll
        for (int ni = 0; ni < 4; ++ni) {
            const int col = bn + wn * 32 + ni * 8 + (lane & 3) * 2;
            if (EPI == 0) {
                float* Y = (float*)Yv;
                *reinterpret_cast<float2*>(&Y[(size_t)row * ldy + col]) =
                    make_float2(acc[mi][ni][0], acc[mi][ni][1]);
                *reinterpret_cast<float2*>(&Y[(size_t)(row + 8) * ldy + col]) =
                    make_float2(acc[mi][ni][2], acc[mi][ni][3]);
            } else {
                __half* Y = (__half*)Yv;
                const float b0 = bias[col], b1 = bias[col + 1];
                __half2 h01, h23;
                h01.x = __float2half_rn(softplus_f(acc[mi][ni][0] + b0));
                h01.y = __float2half_rn(softplus_f(acc[mi][ni][1] + b1));
                h23.x = __float2half_rn(softplus_f(acc[mi][ni][2] + b0));
                h23.y = __float2half_rn(softplus_f(acc[mi][ni][3] + b1));
                *reinterpret_cast<__half2*>(&Y[(size_t)row * ldy + col]) = h01;
                *reinterpret_cast<__half2*>(&Y[(size_t)(row + 8) * ldy + col]) = h23;
            }
        }
    }
}

// ---------------- scan phase A: fused depthwise-conv + per-chunk local scan --------
// Reference recurrence: h[0]=bt[0]*u[0]; h[t]=a[t-1]*h[t-1]+bt[t-1]*u[t-1].
// u computed on-the-fly from x; rounded to fp16 for consistency with phase C reads.
__global__ __launch_bounds__(256)
void scan_phaseA(const float* __restrict__ A_log,
                 const float* __restrict__ x, const float* __restrict__ cw)
{
    const int e = blockIdx.x * 256 + threadIdx.x;
    const int c = blockIdx.y, b = blockIdx.z;
    float A[Nd], invA[Nd];
    bool sm[Nd];
#pragma unroll
    for (int n = 0; n < Nd; ++n) {
        A[n] = -expf(A_log[(size_t)e * Nd + n]);
        invA[n] = 1.f / (A[n] + 1e-10f);
        sm[n] = fabsf(A[n]) < 1e-5f;
    }
    float h[Nd], P[Nd];
#pragma unroll
    for (int n = 0; n < Nd; ++n) { h[n] = 0.f; P[n] = 1.f; }

    const size_t rowbase = (size_t)b * Ld * Ed + e;
    const int l0 = c * CLs;
    const int lprev = (c > 0) ? (l0 - 1) : l0;

    const float4 wcv = *reinterpret_cast<const float4*>(&cw[(size_t)e * Kd]);
    float x0, x1, x2, x3;
    {
        int l = lprev - 3;
        x0 = (l >= 0) ? x[rowbase + (size_t)l * Ed] : 0.f; ++l;
        x1 = (l >= 0) ? x[rowbase + (size_t)l * Ed] : 0.f; ++l;
        x2 = (l >= 0) ? x[rowbase + (size_t)l * Ed] : 0.f; ++l;
        x3 = x[rowbase + (size_t)l * Ed];
    }
    float pu = __half2float(__float2half_rn(
        silu_f(wcv.x * x0 + wcv.y * x1 + wcv.z * x2 + wcv.w * x3)));
    float pd = __half2float(g_dt16[rowbase + (size_t)lprev * Ed]);

    for (int t = 0; t < CLs; ++t) {
#pragma unroll
        for (int n = 0; n < Nd; ++n) {
            const float em1 = expm1_small(pd * A[n]);
            const float a = 1.f + em1;
            const float bt = sm[n] ? pd : em1 * invA[n];
            h[n] = fmaf(a, h[n], bt * pu);
            P[n] *= a;
        }
        const int lcur = l0 + t;
        float ucur;
        if (c == 0 && t == 0) {
            ucur = pu;                      // index 0 reused
        } else {
            x0 = x1; x1 = x2; x2 = x3;
            x3 = x[rowbase + (size_t)lcur * Ed];
            ucur = __half2float(__float2half_rn(
                silu_f(wcv.x * x0 + wcv.y * x1 + wcv.z * x2 + wcv.w * x3)));
        }
        s_uh[rowbase + (size_t)lcur * Ed] = __float2half_rn(ucur);
        pd = __half2float(g_dt16[rowbase + (size_t)lcur * Ed]);
        pu = ucur;
    }
    const size_t ho = (((size_t)b * NCH + c) * Ed + e) * Nd;
#pragma unroll
    for (int n = 0; n < Nd; ++n) { g_hend[ho + n] = h[n]; g_P[ho + n] = P[n]; }
}

// ---------------- scan phase B: combine chunk carries (per b,e,n thread) ----------
__global__ __launch_bounds__(256)
void scan_phaseB()
{
    const int gid = blockIdx.x * 256 + threadIdx.x;   // 0 .. B*E*N-1
    const int n = gid & (Nd - 1);
    const int e = (gid >> 4) & (Ed - 1);
    const int b = gid >> 14;
    float h = 0.f;
    size_t idx = (((size_t)b * NCH) * Ed + e) * Nd + n;
    const size_t stride = (size_t)Ed * Nd;
    for (int c = 0; c < NCH; ++c) {
        g_hcarry[idx] = h;
        h = fmaf(g_P[idx], h, g_hend[idx]);
        idx += stride;
    }
}

// ---------------- scan phase C: rescan with carry, compute y, gate -> gh (fp16) ----
__global__ __launch_bounds__(256)
void scan_phaseC(const float* __restrict__ A_log, const float* __restrict__ Dv)
{
    __shared__ float Cs[CLs][Nd];   // 4 KB, broadcast reads
    const int e = blockIdx.x * 256 + threadIdx.x;
    const int c = blockIdx.y, b = blockIdx.z;
    const size_t tok0 = (size_t)b * Ld + (size_t)c * CLs;
    for (int i = threadIdx.x; i < CLs * Nd; i += 256) {
        const int t = i >> 4, n = i & 15;
        Cs[t][n] = g_C[(tok0 + t) * Nd + n];
    }
    __syncthreads();

    float A[Nd], invA[Nd];
    bool sm[Nd];
#pragma unroll
    for (int n = 0; n < Nd; ++n) {
        A[n] = -expf(A_log[(size_t)e * Nd + n]);
        invA[n] = 1.f / (A[n] + 1e-10f);
        sm[n] = fabsf(A[n]) < 1e-5f;
    }
    float h[Nd];
    const size_t ho = (((size_t)b * NCH + c) * Ed + e) * Nd;
#pragma unroll
    for (int n = 0; n < Nd; ++n) h[n] = g_hcarry[ho + n];
    const float dve = Dv[e];

    const size_t base = tok0 * Ed + e;
    const size_t pidx = (c > 0) ? (base - Ed) : base;
    float pd = __half2float(g_dt16[pidx]);
    float pu = __half2float(s_uh[pidx]);
    for (int t = 0; t < CLs; ++t) {
#pragma unroll
        for (int n = 0; n < Nd; ++n) {
            const float em1 = expm1_small(pd * A[n]);
            const float a = 1.f + em1;
            const float bt = sm[n] ? pd : em1 * invA[n];
            h[n] = fmaf(a, h[n], bt * pu);
        }
        const float d_cur = __half2float(g_dt16[base + (size_t)t * Ed]);
        const float u_cur = __half2float(s_uh[base + (size_t)t * Ed]);
        const float z_cur = __half2float(s_zh[base + (size_t)t * Ed]);
        float y = 0.f;
#pragma unroll
        for (int n = 0; n < Nd; ++n)
            y = fmaf(Cs[t][n], h[n], y);
        const float ys = fmaf(u_cur, dve, y);
        s_gh[base + (size_t)t * Ed] = __float2half_rn(ys * silu_f(z_cur));
        pd = d_cur;
        pu = u_cur;
    }
}

// ---------------- host launcher ----------------
extern "C" void kernel_launch(void* const* d_in, const int* in_sizes, int n_in,
                              void* d_out, int out_size)
{
    const float* x     = (const float*)d_in[0];
    const float* W_z   = (const float*)d_in[1];
    const float* W_p   = (const float*)d_in[2];
    const float* cw    = (const float*)d_in[3];
    const float* W_dt  = (const float*)d_in[4];
    const float* b_dt  = (const float*)d_in[5];
    const float* A_log = (const float*)d_in[6];
    const float* Dv    = (const float*)d_in[7];
    const float* W_o   = (const float*)d_in[8];
    float* out = (float*)d_out;

    float* Cc;
    __half *dt16;
    cudaGetSymbolAddress((void**)&Cc,   g_C);
    cudaGetSymbolAddress((void**)&dt16, g_dt16);

    __half *xh, *zh, *gh, *ph, *wzh, *wph, *wdh, *woh;
    cudaGetSymbolAddress((void**)&xh, s_xh);
    cudaGetSymbolAddress((void**)&zh, s_zh);
    cudaGetSymbolAddress((void**)&gh, s_gh);
    cudaGetSymbolAddress((void**)&ph, s_ph);
    cudaGetSymbolAddress((void**)&wzh, s_wzh);
    cudaGetSymbolAddress((void**)&wph, s_wph);
    cudaGetSymbolAddress((void**)&wdh, s_wdh);
    cudaGetSymbolAddress((void**)&woh, s_woh);

    cudaFuncSetAttribute(gemm_zp,     cudaFuncAttributeMaxDynamicSharedMemorySize, GSM);
    cudaFuncSetAttribute(gemm_gen<0>, cudaFuncAttributeMaxDynamicSharedMemorySize, GSM);
    cudaFuncSetAttribute(gemm_gen<1>, cudaFuncAttributeMaxDynamicSharedMemorySize, GSM);

    dim3 blk(256);

    // single merged cast launch
    cast_all_kernel<<<(CNT + 255) / 256, blk>>>(x, W_z, W_p, W_dt, W_o);

    // merged z + params GEMM (z fp16, ph fp16, compact C)
    gemm_zp<<<dim3(9, Md / 128), blk, GSM>>>(xh, wzh, wph, zh, Cc, ph);
    // dt16 = softplus(params[:, :64] @ W_dt^T + b_dt)   (K=64, fp16 out)
    gemm_gen<1><<<dim3(Ed / 128, Md / 128), blk, GSM>>>(ph, Pd, wdh, Rd,
                                                        dt16, Ed, Rd, b_dt);
    // chunked scan (conv+SiLU fused into phase A)
    scan_phaseA<<<dim3(Ed / 256, NCH, Bd), blk>>>(A_log, x, cw);
    scan_phaseB<<<(Bd * Ed * Nd) / 256, blk>>>();
    scan_phaseC<<<dim3(Ed / 256, NCH, Bd), blk>>>(A_log, Dv);
    // out = g @ W_out^T
    gemm_gen<0><<<dim3(Ed / 128, Md / 128), blk, GSM>>>(gh, Ed, woh, Ed,
                                                        out, Ed, Ed, nullptr);
}